// round 11
// baseline (speedup 1.0000x reference)
#include <cuda_runtime.h>
#include <cuda_fp16.h>
#include <math.h>
#include <stdint.h>

// Problem dims
#define MDIM  16384
#define KDIM  784
#define KPAD  832                  // 13 chunks of 64 (zero padded); rowBytes = 1664
#define NDIM  8192
#define CDIM  10
#define NK1   (NDIM * KDIM)
#define NK2   (CDIM * NDIM)
#define J1    3211264u
#define J2    40960u

// GEMM tiling: CTA 128x256, 256 threads, 8 warps as 2(M)x4(N), warp tile 64x64.
// Split-K fp16 accumulation (even stages -> dh_a, odd -> dh_b), no fp32 shadow.
// All pipeline/LDSM addresses use [reg+imm] PTX to minimize live registers.
#define BM 128
#define BN 256
#define KCH 64
#define NITER 13
#define STAGES 4
#define NT2 (NDIM / BN)            // 32
#define GTHREADS 256

// smem layout
#define OFF_A 0                                   // STAGES x 16384
#define OFF_B (STAGES * 16384)                    // STAGES x 32768
#define OFF_W2 (OFF_B + STAGES * 32768)           // 196608
#define OFF_PART (OFF_W2 + CDIM * BN * 4)         // 206848
#define SMEM_TOTAL (OFF_PART + BM * CDIM * 4)     // 211968

#define SEL_NB 592
#define W1_BLOCKS (NDIM * (KPAD / 4) / 256)       // 6656
#define XH_BLOCKS (MDIM * (KPAD / 8) / 256)       // 6656

// ---------------- scratch ----------------
__device__ __half   g_xh[MDIM * KPAD];
__device__ __half   g_w1h[NDIM * KPAD];
__device__ float    g_w2m[CDIM * NDIM];
__device__ float    g_part[NT2 * MDIM * CDIM];
__device__ unsigned g_h1024[1024];
__device__ unsigned g_prefix;
__device__ unsigned g_rank;
__device__ unsigned g_nLess;
__device__ unsigned g_nTie;
__device__ unsigned g_T[2];
__device__ unsigned g_cutoff[2];
__device__ unsigned g_tieIdx[8192];
__device__ unsigned g_bar_cnt;
__device__ unsigned g_bar_gen;

__device__ __forceinline__ unsigned fbits_abs(float v) {
    return __float_as_uint(fabsf(v));
}
__device__ __forceinline__ uint32_t smem_u32(const void* p) {
    uint32_t a;
    asm("{ .reg .u64 t; cvta.to.shared.u64 t, %1; cvt.u32.u64 %0, t; }" : "=r"(a) : "l"(p));
    return a;
}

// ---------------- software grid barrier ----------------
__device__ __forceinline__ void grid_bar() {
    __syncthreads();
    if (threadIdx.x == 0) {
        unsigned gen = *((volatile unsigned*)&g_bar_gen);
        __threadfence();
        unsigned a = atomicAdd(&g_bar_cnt, 1u);
        if (a == SEL_NB - 1) {
            g_bar_cnt = 0;
            __threadfence();
            atomicAdd(&g_bar_gen, 1u);
        } else {
            while (*((volatile unsigned*)&g_bar_gen) == gen) { }
        }
        __threadfence();
    }
    __syncthreads();
}

// ---------------- persistent exact radix select for s1 ----------------
__global__ void __launch_bounds__(256) k_select(const float* __restrict__ s, int n,
                                                unsigned j, int sel) {
    __shared__ unsigned h[1024];
    __shared__ unsigned sc[256];
    const int tid = threadIdx.x;
    const int gstride = SEL_NB * 256;
    const int gbase = blockIdx.x * 256 + tid;
    const float4* s4 = (const float4*)s;
    const int n4 = n >> 2;

    if (blockIdx.x == 0) {
        for (int b = tid; b < 1024; b += 256) g_h1024[b] = 0u;
        if (tid == 0) { g_prefix = 0u; g_rank = j; g_nLess = 0u; g_nTie = 0u; }
    }
    grid_bar();

#pragma unroll 1
    for (int pass = 0; pass < 3; pass++) {
        const int shift = 20 - 10 * pass;
        const unsigned prefix = g_prefix;
        for (int b = tid; b < 1024; b += 256) h[b] = 0u;
        __syncthreads();
        for (int i = gbase; i < n4; i += gstride) {
            float4 v = s4[i];
            unsigned b0 = fbits_abs(v.x), b1 = fbits_abs(v.y);
            unsigned b2 = fbits_abs(v.z), b3 = fbits_abs(v.w);
            if (pass == 0) {
                atomicAdd(&h[b0 >> 20], 1u); atomicAdd(&h[b1 >> 20], 1u);
                atomicAdd(&h[b2 >> 20], 1u); atomicAdd(&h[b3 >> 20], 1u);
            } else {
                if (((b0 ^ prefix) >> (shift + 10)) == 0u) atomicAdd(&h[(b0 >> shift) & 1023u], 1u);
                if (((b1 ^ prefix) >> (shift + 10)) == 0u) atomicAdd(&h[(b1 >> shift) & 1023u], 1u);
                if (((b2 ^ prefix) >> (shift + 10)) == 0u) atomicAdd(&h[(b2 >> shift) & 1023u], 1u);
                if (((b3 ^ prefix) >> (shift + 10)) == 0u) atomicAdd(&h[(b3 >> shift) & 1023u], 1u);
            }
        }
        __syncthreads();
        for (int b = tid; b < 1024; b += 256)
            if (h[b]) atomicAdd(&g_h1024[b], h[b]);
        grid_bar();

        if (blockIdx.x == 0) {
            unsigned c0 = g_h1024[4 * tid + 0], c1 = g_h1024[4 * tid + 1];
            unsigned c2 = g_h1024[4 * tid + 2], c3 = g_h1024[4 * tid + 3];
            unsigned mysum = c0 + c1 + c2 + c3;
            sc[tid] = mysum;
            __syncthreads();
#pragma unroll
            for (int off = 1; off < 256; off <<= 1) {
                unsigned v = (tid >= off) ? sc[tid - off] : 0u;
                __syncthreads();
                sc[tid] += v;
                __syncthreads();
            }
            unsigned incl = sc[tid], excl = incl - mysum;
            unsigned r = g_rank;
            if (excl <= r && r < incl) {
                unsigned d, cum = excl;
                if (r < cum + c0) { d = 4 * tid + 0; }
                else if (r < cum + c0 + c1) { d = 4 * tid + 1; cum += c0; }
                else if (r < cum + c0 + c1 + c2) { d = 4 * tid + 2; cum += c0 + c1; }
                else { d = 4 * tid + 3; cum += c0 + c1 + c2; }
                g_prefix = g_prefix | (d << shift);
                g_rank = r - cum;
            }
            __syncthreads();
            for (int b = tid; b < 1024; b += 256) g_h1024[b] = 0u;
            __threadfence();
        }
        grid_bar();
    }

    const unsigned T = g_prefix;
    unsigned nless = 0u;
    for (int i = gbase; i < n; i += gstride) {
        unsigned bits = fbits_abs(s[i]);
        if (bits < T) nless++;
        else if (bits == T) {
            unsigned p = atomicAdd(&g_nTie, 1u);
            if (p < 8192u) g_tieIdx[p] = (unsigned)i;
        }
    }
    sc[tid] = nless;
    __syncthreads();
#pragma unroll
    for (int off = 128; off > 0; off >>= 1) {
        if (tid < off) sc[tid] += sc[tid + off];
        __syncthreads();
    }
    if (tid == 0 && sc[0]) atomicAdd(&g_nLess, sc[0]);
    grid_bar();

    if (blockIdx.x == 0) {
        unsigned nLess = g_nLess;
        unsigned nTie = g_nTie; if (nTie > 8192u) nTie = 8192u;
        unsigned r2 = j - nLess;
        if (tid == 0) {
            g_T[sel] = T;
            if (r2 >= nTie) g_cutoff[sel] = 0xFFFFFFFFu;
        }
        __syncthreads();
        if (r2 < nTie) {
            for (unsigned t = tid; t < nTie; t += 256u) {
                unsigned mi = g_tieIdx[t];
                unsigned cnt = 0;
                for (unsigned u = 0; u < nTie; u++) cnt += (g_tieIdx[u] < mi) ? 1u : 0u;
                if (cnt == r2) g_cutoff[sel] = mi;
            }
        }
    }
}

// ---------------- single-block select for s2 + fused w2 mask build ----------------
__global__ void __launch_bounds__(1024) k_select2_w2m(const float* __restrict__ s,
                                                      const float* __restrict__ w2,
                                                      int n, unsigned j) {
    __shared__ unsigned h[1024];
    __shared__ unsigned sc[1024];
    __shared__ unsigned tie[4096];
    __shared__ unsigned sPrefix, sRank, sNTie, sNLess, sCut;
    const int tid = threadIdx.x;
    const float4* s4 = (const float4*)s;
    const int n4 = n >> 2;

    if (tid == 0) { sPrefix = 0u; sRank = j; sNTie = 0u; sNLess = 0u; sCut = 0xFFFFFFFFu; }
    __syncthreads();

#pragma unroll 1
    for (int pass = 0; pass < 3; pass++) {
        const int shift = 20 - 10 * pass;
        const unsigned prefix = sPrefix;
        h[tid] = 0u;
        __syncthreads();
        for (int i = tid; i < n4; i += 1024) {
            float4 v = s4[i];
            unsigned b0 = fbits_abs(v.x), b1 = fbits_abs(v.y);
            unsigned b2 = fbits_abs(v.z), b3 = fbits_abs(v.w);
            if (pass == 0) {
                atomicAdd(&h[b0 >> 20], 1u); atomicAdd(&h[b1 >> 20], 1u);
                atomicAdd(&h[b2 >> 20], 1u); atomicAdd(&h[b3 >> 20], 1u);
            } else {
                if (((b0 ^ prefix) >> (shift + 10)) == 0u) atomicAdd(&h[(b0 >> shift) & 1023u], 1u);
                if (((b1 ^ prefix) >> (shift + 10)) == 0u) atomicAdd(&h[(b1 >> shift) & 1023u], 1u);
                if (((b2 ^ prefix) >> (shift + 10)) == 0u) atomicAdd(&h[(b2 >> shift) & 1023u], 1u);
                if (((b3 ^ prefix) >> (shift + 10)) == 0u) atomicAdd(&h[(b3 >> shift) & 1023u], 1u);
            }
        }
        __syncthreads();
        unsigned mine = h[tid];
        sc[tid] = mine;
        __syncthreads();
#pragma unroll
        for (int off = 1; off < 1024; off <<= 1) {
            unsigned v = (tid >= off) ? sc[tid - off] : 0u;
            __syncthreads();
            sc[tid] += v;
            __syncthreads();
        }
        unsigned incl = sc[tid], excl = incl - mine;
        unsigned r = sRank;
        __syncthreads();
        if (excl <= r && r < incl) {
            sPrefix = prefix | ((unsigned)tid << shift);
            sRank = r - excl;
        }
        __syncthreads();
    }

    const unsigned T = sPrefix;
    unsigned nless = 0u;
    for (int i = tid; i < n; i += 1024) {
        unsigned bits = fbits_abs(s[i]);
        if (bits < T) nless++;
        else if (bits == T) {
            unsigned p = atomicAdd(&sNTie, 1u);
            if (p < 4096u) tie[p] = (unsigned)i;
        }
    }
    sc[tid] = nless;
    __syncthreads();
#pragma unroll
    for (int off = 512; off > 0; off >>= 1) {
        if (tid < off) sc[tid] += sc[tid + off];
        __syncthreads();
    }
    if (tid == 0) sNLess = sc[0];
    __syncthreads();

    {
        unsigned nTie = sNTie; if (nTie > 4096u) nTie = 4096u;
        unsigned r2 = j - sNLess;
        if (r2 < nTie) {
            for (unsigned t = tid; t < nTie; t += 1024u) {
                unsigned mi = tie[t];
                unsigned cnt = 0;
                for (unsigned u = 0; u < nTie; u++) cnt += (tie[u] < mi) ? 1u : 0u;
                if (cnt == r2) sCut = mi;
            }
        }
    }
    __syncthreads();
    const unsigned cut = sCut;
    if (tid == 0) { g_T[1] = T; g_cutoff[1] = cut; }

    for (int i = tid; i < n; i += 1024) {
        unsigned bits = fbits_abs(s[i]);
        bool keep = (bits > T) || (bits == T && (unsigned)i >= cut);
        g_w2m[i] = keep ? w2[i] : 0.0f;
    }
}

// ---------------- fused prep: masked fp16 w1 + fp16 x ----------------
__global__ void __launch_bounds__(256) k_prep(const float* __restrict__ w1,
                                              const float* __restrict__ s1,
                                              const float* __restrict__ x) {
    const int b = blockIdx.x;
    const int tid = threadIdx.x;
    if (b < W1_BLOCKS) {
        int i = b * 256 + tid;
        int row = i / (KPAD / 4), k4 = (i % (KPAD / 4)) * 4;
        __half2 o[2];
        if (k4 < KDIM) {
            int src = row * KDIM + k4;
            float4 w = *(const float4*)(w1 + src);
            float4 sv = *(const float4*)(s1 + src);
            unsigned T = g_T[0], cut = g_cutoff[0];
            unsigned b0 = fbits_abs(sv.x), b1 = fbits_abs(sv.y);
            unsigned b2 = fbits_abs(sv.z), b3 = fbits_abs(sv.w);
            float f0 = ((b0 > T) || (b0 == T && (unsigned)(src + 0) >= cut)) ? w.x : 0.0f;
            float f1 = ((b1 > T) || (b1 == T && (unsigned)(src + 1) >= cut)) ? w.y : 0.0f;
            float f2 = ((b2 > T) || (b2 == T && (unsigned)(src + 2) >= cut)) ? w.z : 0.0f;
            float f3 = ((b3 > T) || (b3 == T && (unsigned)(src + 3) >= cut)) ? w.w : 0.0f;
            o[0] = __floats2half2_rn(f0, f1);
            o[1] = __floats2half2_rn(f2, f3);
        } else {
            o[0] = o[1] = __floats2half2_rn(0.0f, 0.0f);
        }
        *(uint2*)(g_w1h + (size_t)row * KPAD + k4) = *(const uint2*)o;
    } else {
        int i = (b - W1_BLOCKS) * 256 + tid;
        int row = i / (KPAD / 8), u = i % (KPAD / 8);
        int c8 = u * 8;
        __half2 h[4];
        if (c8 < KDIM) {
            const float4* p = (const float4*)(x + (size_t)row * KDIM + c8);
            float4 v0 = p[0], v1 = p[1];
            h[0] = __floats2half2_rn(v0.x, v0.y);
            h[1] = __floats2half2_rn(v0.z, v0.w);
            h[2] = __floats2half2_rn(v1.x, v1.y);
            h[3] = __floats2half2_rn(v1.z, v1.w);
        } else {
            h[0] = h[1] = h[2] = h[3] = __floats2half2_rn(0.0f, 0.0f);
        }
        *(uint4*)(g_xh + (size_t)row * KPAD + c8) = *(const uint4*)h;
    }
}

// ---------------- GEMM helpers (immediate-offset addressing) ----------------
#define CP_COMMIT() asm volatile("cp.async.commit_group;" ::: "memory")
#define CP_WAIT(n)  asm volatile("cp.async.wait_group %0;" :: "n"(n) : "memory")

// cp.async with immediate offsets on both smem dst and gmem src
#define CP16_O(SREG, SOFS, GREG, GOFS) \
    asm volatile("cp.async.cg.shared.global [%0+" SOFS "], [%1+" GOFS "], 16;" \
                 :: "r"(SREG), "l"(GREG))

// ldmatrix x4 with immediate smem offset
#define LDSM4_O(R0, R1, R2, R3, BASE, OFS) \
    asm volatile("ldmatrix.sync.aligned.m8n8.x4.shared.b16 {%0,%1,%2,%3}, [%4+" OFS "];" \
                 : "=r"(R0), "=r"(R1), "=r"(R2), "=r"(R3) : "r"(BASE))

// fp16-accumulating MMA
__device__ __forceinline__ void mma_fp16h(unsigned* d, const unsigned* a, const unsigned* b) {
    asm volatile(
        "mma.sync.aligned.m16n8k16.row.col.f16.f16.f16.f16 "
        "{%0,%1}, {%2,%3,%4,%5}, {%6,%7}, {%0,%1};\n"
        : "+r"(d[0]), "+r"(d[1])
        : "r"(a[0]), "r"(a[1]), "r"(a[2]), "r"(a[3]), "r"(b[0]), "r"(b[1]));
}

__device__ __forceinline__ uint32_t sw_off(uint32_t row, uint32_t u) {
    return row * 128u + ((u ^ (row & 7u)) << 4);
}

// ---------------- GEMM1: 256 threads, 8 warps of 64x64, split-K fp16 acc,
//  all addresses via [reg+imm] -> minimal live registers, no spill. ----------------
__global__ void __launch_bounds__(GTHREADS, 1) k_gemm1() {
    extern __shared__ __align__(1024) char smem[];
    const uint32_t sb = smem_u32(smem);
    const int tid = threadIdx.x;
    const int nt = blockIdx.x;   // 0..31
    const int mt = blockIdx.y;   // 0..127

    const int wid = tid >> 5, lane = tid & 31;
    const int mw = wid & 1;
    const int nw = wid >> 1;
    const int g4 = lane >> 2, t4 = lane & 3;
    const int r8 = lane & 7;

    float* W2s  = (float*)(smem + OFF_W2);
    float* Part = (float*)(smem + OFF_PART);
    for (int p = tid; p < CDIM * BN; p += GTHREADS)
        W2s[p] = g_w2m[(p >> 8) * NDIM + nt * BN + (p & 255)];
    for (int p = tid; p < BM * CDIM; p += GTHREADS)
        Part[p] = 0.0f;

    // per-thread invariant bases (rowBytes = 1664; 32 rows = 53248 bytes)
    const char* aG0 = (const char*)(g_xh  + (size_t)(mt * BM) * KPAD)
                      + (size_t)(tid >> 3) * 1664 + (tid & 7) * 16;
    const char* bG0 = (const char*)(g_w1h + (size_t)(nt * BN) * KPAD)
                      + (size_t)(tid >> 3) * 1664 + (tid & 7) * 16;
    const uint32_t sA0 = sb + OFF_A + sw_off((uint32_t)(tid >> 3), (uint32_t)(tid & 7));
    const uint32_t sB0 = sb + OFF_B + sw_off((uint32_t)(tid >> 3), (uint32_t)(tid & 7));

    const uint32_t aRowL = (uint32_t)(mw * 64 + ((lane >> 3) & 1) * 8 + r8);
    const uint32_t uA    = (uint32_t)(lane >> 4);
    const uint32_t bRowL = (uint32_t)(nw * 64 + (lane >> 4) * 8 + r8);
    const uint32_t uB    = (uint32_t)((lane >> 3) & 1);

    // split-K fp16 accumulator sets (64 regs each)
    unsigned dh_a[4][8][2], dh_b[4][8][2];
#pragma unroll
    for (int i = 0; i < 4; i++)
#pragma unroll
        for (int j = 0; j < 8; j++) {
            dh_a[i][j][0] = 0u; dh_a[i][j][1] = 0u;
            dh_b[i][j][0] = 0u; dh_b[i][j][1] = 0u;
        }

// A: 4 x cp16 at q*4096 smem / q*53248 gmem. B: 8 x cp16.
#define ISSUE_STAGE(st) do {                                                      \
    const uint32_t _sA = sA0 + ((st) & 3) * 16384;                                \
    const char*    _gA = aG0 + (size_t)(st) * 128;                                \
    CP16_O(_sA, "0",     _gA, "0");                                               \
    CP16_O(_sA, "4096",  _gA, "53248");                                           \
    CP16_O(_sA, "8192",  _gA, "106496");                                          \
    CP16_O(_sA, "12288", _gA, "159744");                                          \
    const uint32_t _sB = sB0 + ((st) & 3) * 32768;                                \
    const char*    _gB = bG0 + (size_t)(st) * 128;                                \
    CP16_O(_sB, "0",     _gB, "0");                                               \
    CP16_O(_sB, "4096",  _gB, "53248");                                           \
    CP16_O(_sB, "8192",  _gB, "106496");                                          \
    CP16_O(_sB, "12288", _gB, "159744");                                          \
    CP16_O(_sB, "16384", _gB, "212992");                                          \
    CP16_O(_sB, "20480", _gB, "266240");                                          \
    CP16_O(_sB, "24576", _gB, "319488");                                          \
    CP16_O(_sB, "28672", _gB, "372736");                                          \
} while (0)

// one K=64 pipeline stage into accumulator set DH; A/B LDSM at imm offsets i*2048
#define STAGE(kk, DH) do {                                                        \
    CP_WAIT(2);                                                                   \
    __syncthreads();                                                              \
    const int _nx = (kk) + 3;                                                     \
    if (_nx < NITER) ISSUE_STAGE(_nx);                                            \
    CP_COMMIT();                                                                  \
    const uint32_t _aB = sb + OFF_A + ((kk) & 3) * 16384;                         \
    const uint32_t _bB = sb + OFF_B + ((kk) & 3) * 32768;                         \
    _Pragma("unroll")                                                             \
    for (int ks = 0; ks < 4; ks++) {                                              \
        const uint32_t _ul = (uint32_t)(2 * ks);                                  \
        unsigned A4[4][4], B4[4][4];                                              \
        const uint32_t _aAd = _aB + sw_off(aRowL, _ul + uA);                      \
        LDSM4_O(A4[0][0], A4[0][1], A4[0][2], A4[0][3], _aAd, "0");               \
        LDSM4_O(A4[1][0], A4[1][1], A4[1][2], A4[1][3], _aAd, "2048");            \
        LDSM4_O(A4[2][0], A4[2][1], A4[2][2], A4[2][3], _aAd, "4096");            \
        LDSM4_O(A4[3][0], A4[3][1], A4[3][2], A4[3][3], _aAd, "6144");            \
        const uint32_t _bAd = _bB + sw_off(bRowL, _ul + uB);                      \
        LDSM4_O(B4[0][0], B4[0][1], B4[0][2], B4[0][3], _bAd, "0");               \
        LDSM4_O(B4[1][0], B4[1][1], B4[1][2], B4[1][3], _bAd, "2048");            \
        LDSM4_O(B4[2][0], B4[2][1], B4[2][2], B4[2][3], _bAd, "4096");            \
        LDSM4_O(B4[3][0], B4[3][1], B4[3][2], B4[3][3], _bAd, "6144");            \
        _Pragma("unroll")                                                         \
        for (int i = 0; i < 4; i++)                                               \
            _Pragma("unroll")                                                     \
            for (int j = 0; j < 8; j++)                                           \
                mma_fp16h(DH[i][j], A4[i], &B4[j >> 1][2 * (j & 1)]);             \
    }                                                                             \
} while (0)

    ISSUE_STAGE(0); CP_COMMIT();
    ISSUE_STAGE(1); CP_COMMIT();
    ISSUE_STAGE(2); CP_COMMIT();

#pragma unroll 1
    for (int kb = 0; kb < 6; kb++) {
        STAGE(2 * kb + 0, dh_a);
        STAGE(2 * kb + 1, dh_b);
    }
    STAGE(12, dh_a);

    // ---- epilogue: combine halves in fp32, relu, contract with w2 slice ----
#pragma unroll
    for (int i = 0; i < 4; i++) {
#pragma unroll
        for (int h = 0; h < 2; h++) {
            const int row = mw * 64 + i * 16 + g4 + h * 8;
            float v0[8], v1[8];
#pragma unroll
            for (int j = 0; j < 8; j++) {
                float2 fa = __half22float2(*(const __half2*)&dh_a[i][j][h]);
                float2 fb = __half22float2(*(const __half2*)&dh_b[i][j][h]);
                v0[j] = fmaxf(fa.x + fb.x, 0.0f);
                v1[j] = fmaxf(fa.y + fb.y, 0.0f);
            }
#pragma unroll
            for (int c = 0; c < CDIM; c++) {
                float s = 0.0f;
#pragma unroll
                for (int j = 0; j < 8; j++) {
                    float2 w = *(const float2*)&W2s[c * BN + nw * 64 + j * 8 + 2 * t4];
                    s += v0[j] * w.x + v1[j] * w.y;
                }
                s += __shfl_xor_sync(0xFFFFFFFFu, s, 1);
                s += __shfl_xor_sync(0xFFFFFFFFu, s, 2);
                if (t4 == 0) atomicAdd(&Part[row * CDIM + c], s);
            }
        }
    }
    __syncthreads();

    float* outp = g_part + (size_t)nt * (MDIM * CDIM) + (size_t)(mt * BM) * CDIM;
    for (int p = tid; p < BM * CDIM; p += GTHREADS) outp[p] = Part[p];
#undef STAGE
#undef ISSUE_STAGE
}

// ---------------- reduce partials + log_softmax ----------------
__global__ void k_reduce(float* __restrict__ out) {   // <<<512, 320>>>
    const int tid = threadIdx.x;
    const int base = blockIdx.x * 32 * CDIM;
    float s = 0.0f;
#pragma unroll 8
    for (int nt = 0; nt < NT2; nt++)
        s += g_part[(size_t)nt * (MDIM * CDIM) + base + tid];
    __shared__ float L[32 * CDIM];
    L[tid] = s;
    __syncthreads();
    const int rl = tid / CDIM;
    float m = -INFINITY;
#pragma unroll
    for (int c = 0; c < CDIM; c++) m = fmaxf(m, L[rl * CDIM + c]);
    float se = 0.0f;
#pragma unroll
    for (int c = 0; c < CDIM; c++) se += expf(L[rl * CDIM + c] - m);
    out[base + tid] = s - m - logf(se);
}

// ---------------- launch ----------------
extern "C" void kernel_launch(void* const* d_in, const int* in_sizes, int n_in,
                              void* d_out, int out_size) {
    const float* x  = (const float*)d_in[0];
    const float* w1 = (const float*)d_in[1];
    const float* s1 = (const float*)d_in[2];
    const float* w2 = (const float*)d_in[3];
    const float* s2 = (const float*)d_in[4];
    float* out = (float*)d_out;

    cudaFuncSetAttribute(k_gemm1, cudaFuncAttributeMaxDynamicSharedMemorySize, SMEM_TOTAL);

    // launch order is load-bearing: ncu captures launch index 3 -> k_gemm1.
    k_select<<<SEL_NB, 256>>>(s1, NK1, J1, 0);                       // 0
    k_select2_w2m<<<1, 1024>>>(s2, w2, NK2, J2);                     // 1
    k_prep<<<W1_BLOCKS + XH_BLOCKS, 256>>>(w1, s1, x);               // 2
    dim3 grid(NT2, MDIM / BM);   // (32, 128)
    k_gemm1<<<grid, GTHREADS, SMEM_TOTAL>>>();                       // 3  <- ncu target
    k_reduce<<<MDIM / 32, 32 * CDIM>>>(out);                         // 4
}

// round 12
// speedup vs baseline: 1.0163x; 1.0163x over previous
#include <cuda_runtime.h>
#include <cuda_fp16.h>
#include <math.h>
#include <stdint.h>

// Problem dims
#define MDIM  16384
#define KDIM  784                  // used exactly: 12 full K64 stages + 1 K16 stage
#define NDIM  8192
#define CDIM  10
#define NK1   (NDIM * KDIM)
#define NK2   (CDIM * NDIM)
#define J1    3211264u
#define J2    40960u

// GEMM tiling: CTA 128x256, 256 threads, 8 warps as 2(M)x4(N), warp tile 64x64, fp32 acc.
#define BM 128
#define BN 256
#define NT2 (NDIM / BN)            // 32
#define GTHREADS 256
#define ROWB 1568                  // KDIM * 2 bytes
#define ROW32 50176                // 32 * ROWB

// smem layout
#define OFF_A 0                                   // 4 x 16384
#define OFF_B (4 * 16384)                         // 4 x 32768
#define OFF_W2 (OFF_B + 4 * 32768)                // 196608
#define OFF_PART (OFF_W2 + CDIM * BN * 4)         // 206848
#define SMEM_TOTAL (OFF_PART + BM * CDIM * 4)     // 211968

#define SEL_NB 592
#define CAND_MAX 32768
#define W1_BLOCKS (NDIM * (KDIM / 4) / 256)       // 6272
#define XH_BLOCKS (MDIM * (KDIM / 8) / 256)       // 6272

// ---------------- scratch ----------------
__device__ __half   g_xh[MDIM * KDIM];
__device__ __half   g_w1h[NDIM * KDIM];
__device__ float    g_w2m[CDIM * NDIM];
__device__ float    g_part[NT2 * MDIM * CDIM];
__device__ unsigned g_h1024[1024];
__device__ unsigned g_prefix;
__device__ unsigned g_rank;
__device__ unsigned g_nCand;
__device__ unsigned g_T[2];
__device__ unsigned g_cutoff[2];
__device__ unsigned g_candIdx[CAND_MAX];
__device__ unsigned g_candBits[CAND_MAX];
__device__ unsigned g_bar_cnt;
__device__ unsigned g_bar_gen;

__device__ __forceinline__ unsigned fbits_abs(float v) {
    return __float_as_uint(fabsf(v));
}
__device__ __forceinline__ uint32_t smem_u32(const void* p) {
    uint32_t a;
    asm("{ .reg .u64 t; cvta.to.shared.u64 t, %1; cvt.u32.u64 %0, t; }" : "=r"(a) : "l"(p));
    return a;
}

// ---------------- software grid barrier ----------------
__device__ __forceinline__ void grid_bar() {
    __syncthreads();
    if (threadIdx.x == 0) {
        unsigned gen = *((volatile unsigned*)&g_bar_gen);
        __threadfence();
        unsigned a = atomicAdd(&g_bar_cnt, 1u);
        if (a == SEL_NB - 1) {
            g_bar_cnt = 0;
            __threadfence();
            atomicAdd(&g_bar_gen, 1u);
        } else {
            while (*((volatile unsigned*)&g_bar_gen) == gen) { }
        }
        __threadfence();
    }
    __syncthreads();
}

// ---------------- persistent exact radix select for s1: 3 scans total ----------------
// Pass 3 gathers all elements matching the 20-bit prefix; final g_rank telescopes to
// the tie rank (j - #less), so no nLess reduction and no 4th (tie) scan are needed.
__global__ void __launch_bounds__(256) k_select(const float* __restrict__ s, int n,
                                                unsigned j, int sel) {
    __shared__ unsigned h[1024];
    __shared__ unsigned sc[256];
    const int tid = threadIdx.x;
    const int gstride = SEL_NB * 256;
    const int gbase = blockIdx.x * 256 + tid;
    const float4* s4 = (const float4*)s;
    const int n4 = n >> 2;

    if (blockIdx.x == 0) {
        for (int b = tid; b < 1024; b += 256) g_h1024[b] = 0u;
        if (tid == 0) { g_prefix = 0u; g_rank = j; g_nCand = 0u; }
    }
    grid_bar();

#pragma unroll 1
    for (int pass = 0; pass < 3; pass++) {
        const int shift = 20 - 10 * pass;
        const unsigned prefix = g_prefix;
        for (int b = tid; b < 1024; b += 256) h[b] = 0u;
        __syncthreads();
        for (int i = gbase; i < n4; i += gstride) {
            float4 v = s4[i];
            unsigned bb[4];
            bb[0] = fbits_abs(v.x); bb[1] = fbits_abs(v.y);
            bb[2] = fbits_abs(v.z); bb[3] = fbits_abs(v.w);
            if (pass == 0) {
                atomicAdd(&h[bb[0] >> 20], 1u); atomicAdd(&h[bb[1] >> 20], 1u);
                atomicAdd(&h[bb[2] >> 20], 1u); atomicAdd(&h[bb[3] >> 20], 1u);
            } else if (pass == 1) {
#pragma unroll
                for (int c = 0; c < 4; c++)
                    if (((bb[c] ^ prefix) >> 20) == 0u)
                        atomicAdd(&h[(bb[c] >> 10) & 1023u], 1u);
            } else {
#pragma unroll
                for (int c = 0; c < 4; c++) {
                    if (((bb[c] ^ prefix) >> 10) == 0u) {
                        atomicAdd(&h[bb[c] & 1023u], 1u);
                        unsigned p = atomicAdd(&g_nCand, 1u);
                        if (p < CAND_MAX) {
                            g_candIdx[p] = (unsigned)(4 * i + c);
                            g_candBits[p] = bb[c];
                        }
                    }
                }
            }
        }
        __syncthreads();
        for (int b = tid; b < 1024; b += 256)
            if (h[b]) atomicAdd(&g_h1024[b], h[b]);
        grid_bar();

        if (blockIdx.x == 0) {
            unsigned c0 = g_h1024[4 * tid + 0], c1 = g_h1024[4 * tid + 1];
            unsigned c2 = g_h1024[4 * tid + 2], c3 = g_h1024[4 * tid + 3];
            unsigned mysum = c0 + c1 + c2 + c3;
            sc[tid] = mysum;
            __syncthreads();
#pragma unroll
            for (int off = 1; off < 256; off <<= 1) {
                unsigned v = (tid >= off) ? sc[tid - off] : 0u;
                __syncthreads();
                sc[tid] += v;
                __syncthreads();
            }
            unsigned incl = sc[tid], excl = incl - mysum;
            unsigned r = g_rank;
            if (excl <= r && r < incl) {
                unsigned d, cum = excl;
                if (r < cum + c0) { d = 4 * tid + 0; }
                else if (r < cum + c0 + c1) { d = 4 * tid + 1; cum += c0; }
                else if (r < cum + c0 + c1 + c2) { d = 4 * tid + 2; cum += c0 + c1; }
                else { d = 4 * tid + 3; cum += c0 + c1 + c2; }
                g_prefix = g_prefix | (d << shift);
                g_rank = r - cum;
            }
            __syncthreads();
            for (int b = tid; b < 1024; b += 256) g_h1024[b] = 0u;
            __threadfence();
        }
        grid_bar();
    }

    // block 0: filter candidates for exact ties (== T); g_rank == tie rank (stable argsort)
    if (blockIdx.x == 0) {
        const unsigned T = g_prefix;
        const unsigned r2 = g_rank;
        if (tid == 0) { g_T[sel] = T; g_cutoff[sel] = 0xFFFFFFFFu; }
        __syncthreads();
        unsigned nc = g_nCand; if (nc > CAND_MAX) nc = CAND_MAX;
        for (unsigned t = tid; t < nc; t += 256u) {
            if (g_candBits[t] == T) {
                unsigned mi = g_candIdx[t];
                unsigned cnt = 0;
                for (unsigned u = 0; u < nc; u++)
                    cnt += (g_candBits[u] == T && g_candIdx[u] < mi) ? 1u : 0u;
                if (cnt == r2) g_cutoff[sel] = mi;
            }
        }
    }
}

// ---------------- single-block select for s2 + fused w2 mask build ----------------
__global__ void __launch_bounds__(1024) k_select2_w2m(const float* __restrict__ s,
                                                      const float* __restrict__ w2,
                                                      int n, unsigned j) {
    __shared__ unsigned h[1024];
    __shared__ unsigned sc[1024];
    __shared__ unsigned tie[4096];
    __shared__ unsigned sPrefix, sRank, sNTie, sNLess, sCut;
    const int tid = threadIdx.x;
    const float4* s4 = (const float4*)s;
    const int n4 = n >> 2;

    if (tid == 0) { sPrefix = 0u; sRank = j; sNTie = 0u; sNLess = 0u; sCut = 0xFFFFFFFFu; }
    __syncthreads();

#pragma unroll 1
    for (int pass = 0; pass < 3; pass++) {
        const int shift = 20 - 10 * pass;
        const unsigned prefix = sPrefix;
        h[tid] = 0u;
        __syncthreads();
        for (int i = tid; i < n4; i += 1024) {
            float4 v = s4[i];
            unsigned b0 = fbits_abs(v.x), b1 = fbits_abs(v.y);
            unsigned b2 = fbits_abs(v.z), b3 = fbits_abs(v.w);
            if (pass == 0) {
                atomicAdd(&h[b0 >> 20], 1u); atomicAdd(&h[b1 >> 20], 1u);
                atomicAdd(&h[b2 >> 20], 1u); atomicAdd(&h[b3 >> 20], 1u);
            } else {
                if (((b0 ^ prefix) >> (shift + 10)) == 0u) atomicAdd(&h[(b0 >> shift) & 1023u], 1u);
                if (((b1 ^ prefix) >> (shift + 10)) == 0u) atomicAdd(&h[(b1 >> shift) & 1023u], 1u);
                if (((b2 ^ prefix) >> (shift + 10)) == 0u) atomicAdd(&h[(b2 >> shift) & 1023u], 1u);
                if (((b3 ^ prefix) >> (shift + 10)) == 0u) atomicAdd(&h[(b3 >> shift) & 1023u], 1u);
            }
        }
        __syncthreads();
        unsigned mine = h[tid];
        sc[tid] = mine;
        __syncthreads();
#pragma unroll
        for (int off = 1; off < 1024; off <<= 1) {
            unsigned v = (tid >= off) ? sc[tid - off] : 0u;
            __syncthreads();
            sc[tid] += v;
            __syncthreads();
        }
        unsigned incl = sc[tid], excl = incl - mine;
        unsigned r = sRank;
        __syncthreads();
        if (excl <= r && r < incl) {
            sPrefix = prefix | ((unsigned)tid << shift);
            sRank = r - excl;
        }
        __syncthreads();
    }

    const unsigned T = sPrefix;
    unsigned nless = 0u;
    for (int i = tid; i < n; i += 1024) {
        unsigned bits = fbits_abs(s[i]);
        if (bits < T) nless++;
        else if (bits == T) {
            unsigned p = atomicAdd(&sNTie, 1u);
            if (p < 4096u) tie[p] = (unsigned)i;
        }
    }
    sc[tid] = nless;
    __syncthreads();
#pragma unroll
    for (int off = 512; off > 0; off >>= 1) {
        if (tid < off) sc[tid] += sc[tid + off];
        __syncthreads();
    }
    if (tid == 0) sNLess = sc[0];
    __syncthreads();

    {
        unsigned nTie = sNTie; if (nTie > 4096u) nTie = 4096u;
        unsigned r2 = j - sNLess;
        if (r2 < nTie) {
            for (unsigned t = tid; t < nTie; t += 1024u) {
                unsigned mi = tie[t];
                unsigned cnt = 0;
                for (unsigned u = 0; u < nTie; u++) cnt += (tie[u] < mi) ? 1u : 0u;
                if (cnt == r2) sCut = mi;
            }
        }
    }
    __syncthreads();
    const unsigned cut = sCut;
    if (tid == 0) { g_T[1] = T; g_cutoff[1] = cut; }

    for (int i = tid; i < n; i += 1024) {
        unsigned bits = fbits_abs(s[i]);
        bool keep = (bits > T) || (bits == T && (unsigned)i >= cut);
        g_w2m[i] = keep ? w2[i] : 0.0f;
    }
}

// ---------------- fused prep: masked fp16 w1 + fp16 x (K = 784 exactly) ----------------
__global__ void __launch_bounds__(256) k_prep(const float* __restrict__ w1,
                                              const float* __restrict__ s1,
                                              const float* __restrict__ x) {
    const int b = blockIdx.x;
    const int tid = threadIdx.x;
    if (b < W1_BLOCKS) {
        int i = b * 256 + tid;                    // 4 elems per thread
        int src = i * 4;
        float4 w = *(const float4*)(w1 + src);
        float4 sv = *(const float4*)(s1 + src);
        unsigned T = g_T[0], cut = g_cutoff[0];
        unsigned b0 = fbits_abs(sv.x), b1 = fbits_abs(sv.y);
        unsigned b2 = fbits_abs(sv.z), b3 = fbits_abs(sv.w);
        float f0 = ((b0 > T) || (b0 == T && (unsigned)(src + 0) >= cut)) ? w.x : 0.0f;
        float f1 = ((b1 > T) || (b1 == T && (unsigned)(src + 1) >= cut)) ? w.y : 0.0f;
        float f2 = ((b2 > T) || (b2 == T && (unsigned)(src + 2) >= cut)) ? w.z : 0.0f;
        float f3 = ((b3 > T) || (b3 == T && (unsigned)(src + 3) >= cut)) ? w.w : 0.0f;
        __half2 o[2];
        o[0] = __floats2half2_rn(f0, f1);
        o[1] = __floats2half2_rn(f2, f3);
        *(uint2*)(g_w1h + src) = *(const uint2*)o;
    } else {
        int i = (b - W1_BLOCKS) * 256 + tid;      // 8 halves per thread
        int src = i * 8;
        const float4* p = (const float4*)(x + src);
        float4 v0 = p[0], v1 = p[1];
        __half2 h[4];
        h[0] = __floats2half2_rn(v0.x, v0.y);
        h[1] = __floats2half2_rn(v0.z, v0.w);
        h[2] = __floats2half2_rn(v1.x, v1.y);
        h[3] = __floats2half2_rn(v1.z, v1.w);
        *(uint4*)(g_xh + src) = *(const uint4*)h;
    }
}

// ---------------- GEMM helpers (immediate-offset addressing) ----------------
#define CP_COMMIT() asm volatile("cp.async.commit_group;" ::: "memory")
#define CP_WAIT(n)  asm volatile("cp.async.wait_group %0;" :: "n"(n) : "memory")

#define CP16_O(SREG, SOFS, GREG, GOFS) \
    asm volatile("cp.async.cg.shared.global [%0+" SOFS "], [%1+" GOFS "], 16;" \
                 :: "r"(SREG), "l"(GREG))

#define LDSM4_O(R0, R1, R2, R3, BASE, OFS) \
    asm volatile("ldmatrix.sync.aligned.m8n8.x4.shared.b16 {%0,%1,%2,%3}, [%4+" OFS "];" \
                 : "=r"(R0), "=r"(R1), "=r"(R2), "=r"(R3) : "r"(BASE))

__device__ __forceinline__ void mma_fp16(float* d, const unsigned* a, const unsigned* b) {
    asm volatile(
        "mma.sync.aligned.m16n8k16.row.col.f32.f16.f16.f32 "
        "{%0,%1,%2,%3}, {%4,%5,%6,%7}, {%8,%9}, {%0,%1,%2,%3};\n"
        : "+f"(d[0]), "+f"(d[1]), "+f"(d[2]), "+f"(d[3])
        : "r"(a[0]), "r"(a[1]), "r"(a[2]), "r"(a[3]), "r"(b[0]), "r"(b[1]));
}

__device__ __forceinline__ uint32_t sw_off(uint32_t row, uint32_t u) {
    return row * 128u + ((u ^ (row & 7u)) << 4);
}

// ---------------- GEMM1: fp32 acc, K = 784 = 12 full K64 stages + 1 K16 stage ----------------
__global__ void __launch_bounds__(GTHREADS, 1) k_gemm1() {
    extern __shared__ __align__(1024) char smem[];
    const uint32_t sb = smem_u32(smem);
    const int tid = threadIdx.x;
    const int nt = blockIdx.x;   // 0..31
    const int mt = blockIdx.y;   // 0..127

    const int wid = tid >> 5, lane = tid & 31;
    const int mw = wid & 1;
    const int nw = wid >> 1;
    const int g4 = lane >> 2, t4 = lane & 3;
    const int r8 = lane & 7;

    float* W2s  = (float*)(smem + OFF_W2);
    float* Part = (float*)(smem + OFF_PART);
    for (int p = tid; p < CDIM * BN; p += GTHREADS)
        W2s[p] = g_w2m[(p >> 8) * NDIM + nt * BN + (p & 255)];
    for (int p = tid; p < BM * CDIM; p += GTHREADS)
        Part[p] = 0.0f;

    // per-thread invariant bases (rowBytes = 1568; 32 rows = 50176 bytes)
    const char* aG0 = (const char*)(g_xh  + (size_t)(mt * BM) * KDIM)
                      + (size_t)(tid >> 3) * ROWB + (tid & 7) * 16;
    const char* bG0 = (const char*)(g_w1h + (size_t)(nt * BN) * KDIM)
                      + (size_t)(tid >> 3) * ROWB + (tid & 7) * 16;
    const uint32_t sA0 = sb + OFF_A + sw_off((uint32_t)(tid >> 3), (uint32_t)(tid & 7));
    const uint32_t sB0 = sb + OFF_B + sw_off((uint32_t)(tid >> 3), (uint32_t)(tid & 7));

    const uint32_t aRowL = (uint32_t)(mw * 64 + ((lane >> 3) & 1) * 8 + r8);
    const uint32_t uA    = (uint32_t)(lane >> 4);
    const uint32_t bRowL = (uint32_t)(nw * 64 + (lane >> 4) * 8 + r8);
    const uint32_t uB    = (uint32_t)((lane >> 3) & 1);

    float d[4][8][4];
#pragma unroll
    for (int i = 0; i < 4; i++)
#pragma unroll
        for (int j = 0; j < 8; j++)
#pragma unroll
            for (int r = 0; r < 4; r++) d[i][j][r] = 0.0f;

#define ISSUE_STAGE(st) do {                                                      \
    const uint32_t _sA = sA0 + ((st) & 3) * 16384;                                \
    const char*    _gA = aG0 + (size_t)(st) * 128;                                \
    CP16_O(_sA, "0",     _gA, "0");                                               \
    CP16_O(_sA, "4096",  _gA, "50176");                                           \
    CP16_O(_sA, "8192",  _gA, "100352");                                          \
    CP16_O(_sA, "12288", _gA, "150528");                                          \
    const uint32_t _sB = sB0 + ((st) & 3) * 32768;                                \
    const char*    _gB = bG0 + (size_t)(st) * 128;                                \
    CP16_O(_sB, "0",     _gB, "0");                                               \
    CP16_O(_sB, "4096",  _gB, "50176");                                           \
    CP16_O(_sB, "8192",  _gB, "100352");                                          \
    CP16_O(_sB, "12288", _gB, "150528");                                          \
    CP16_O(_sB, "16384", _gB, "200704");                                          \
    CP16_O(_sB, "20480", _gB, "250880");                                          \
    CP16_O(_sB, "24576", _gB, "301056");                                          \
    CP16_O(_sB, "28672", _gB, "351232");                                          \
} while (0)

// one K=16 slice (logical unit pair ul, ul+1) from slot bases
#define COMPUTE_KS(_aB, _bB, ksv) do {                                            \
    const uint32_t _ul = (uint32_t)(2 * (ksv));                                   \
    unsigned A4[4][4], B4[4][4];                                                  \
    const uint32_t _aAd = (_aB) + sw_off(aRowL, _ul + uA);                        \
    LDSM4_O(A4[0][0], A4[0][1], A4[0][2], A4[0][3], _aAd, "0");                   \
    LDSM4_O(A4[1][0], A4[1][1], A4[1][2], A4[1][3], _aAd, "2048");                \
    LDSM4_O(A4[2][0], A4[2][1], A4[2][2], A4[2][3], _aAd, "4096");                \
    LDSM4_O(A4[3][0], A4[3][1], A4[3][2], A4[3][3], _aAd, "6144");                \
    const uint32_t _bAd = (_bB) + sw_off(bRowL, _ul + uB);                        \
    LDSM4_O(B4[0][0], B4[0][1], B4[0][2], B4[0][3], _bAd, "0");                   \
    LDSM4_O(B4[1][0], B4[1][1], B4[1][2], B4[1][3], _bAd, "2048");                \
    LDSM4_O(B4[2][0], B4[2][1], B4[2][2], B4[2][3], _bAd, "4096");                \
    LDSM4_O(B4[3][0], B4[3][1], B4[3][2], B4[3][3], _bAd, "6144");                \
    _Pragma("unroll")                                                             \
    for (int i = 0; i < 4; i++)                                                   \
        _Pragma("unroll")                                                         \
        for (int j = 0; j < 8; j++)                                               \
            mma_fp16(d[i][j], A4[i], &B4[j >> 1][2 * (j & 1)]);                   \
} while (0)

#define COMPUTE_STAGE(kk) do {                                                    \
    const uint32_t _aB = sb + OFF_A + ((kk) & 3) * 16384;                         \
    const uint32_t _bB = sb + OFF_B + ((kk) & 3) * 32768;                         \
    COMPUTE_KS(_aB, _bB, 0);                                                      \
    COMPUTE_KS(_aB, _bB, 1);                                                      \
    COMPUTE_KS(_aB, _bB, 2);                                                      \
    COMPUTE_KS(_aB, _bB, 3);                                                      \
} while (0)

    ISSUE_STAGE(0); CP_COMMIT();
    ISSUE_STAGE(1); CP_COMMIT();
    ISSUE_STAGE(2); CP_COMMIT();

    // stages 0..8: full compute, full issue of kk+3 (stages 3..11)
#pragma unroll 1
    for (int kk = 0; kk < 9; kk++) {
        CP_WAIT(2);
        __syncthreads();
        ISSUE_STAGE(kk + 3);
        CP_COMMIT();
        COMPUTE_STAGE(kk);
    }
    // stage 9: issue partial stage 12 (only logical units 0,1 -> K16 tail)
    CP_WAIT(2);
    __syncthreads();
    if ((tid & 7) < 2) ISSUE_STAGE(12);
    CP_COMMIT();
    COMPUTE_STAGE(9);
    // stage 10
    CP_WAIT(2);
    __syncthreads();
    CP_COMMIT();
    COMPUTE_STAGE(10);
    // stage 11
    CP_WAIT(2);
    __syncthreads();
    CP_COMMIT();
    COMPUTE_STAGE(11);
    // stage 12: K16 only (slot 0, ks=0)
    CP_WAIT(0);
    __syncthreads();
    {
        const uint32_t _aB = sb + OFF_A + 0 * 16384;
        const uint32_t _bB = sb + OFF_B + 0 * 32768;
        COMPUTE_KS(_aB, _bB, 0);
    }

    // ---- epilogue: relu + contract with w2 slice ----
#pragma unroll
    for (int i = 0; i < 4; i++) {
#pragma unroll
        for (int h = 0; h < 2; h++) {
            const int row = mw * 64 + i * 16 + g4 + h * 8;
            float v0[8], v1[8];
#pragma unroll
            for (int j = 0; j < 8; j++) {
                v0[j] = fmaxf(d[i][j][2 * h + 0], 0.0f);
                v1[j] = fmaxf(d[i][j][2 * h + 1], 0.0f);
            }
#pragma unroll
            for (int c = 0; c < CDIM; c++) {
                float s = 0.0f;
#pragma unroll
                for (int j = 0; j < 8; j++) {
                    float2 w = *(const float2*)&W2s[c * BN + nw * 64 + j * 8 + 2 * t4];
                    s += v0[j] * w.x + v1[j] * w.y;
                }
                s += __shfl_xor_sync(0xFFFFFFFFu, s, 1);
                s += __shfl_xor_sync(0xFFFFFFFFu, s, 2);
                if (t4 == 0) atomicAdd(&Part[row * CDIM + c], s);
            }
        }
    }
    __syncthreads();

    float* outp = g_part + (size_t)nt * (MDIM * CDIM) + (size_t)(mt * BM) * CDIM;
    for (int p = tid; p < BM * CDIM; p += GTHREADS) outp[p] = Part[p];
#undef COMPUTE_STAGE
#undef COMPUTE_KS
#undef ISSUE_STAGE
}

// ---------------- reduce partials + log_softmax ----------------
__global__ void k_reduce(float* __restrict__ out) {   // <<<512, 320>>>
    const int tid = threadIdx.x;
    const int base = blockIdx.x * 32 * CDIM;
    float s = 0.0f;
#pragma unroll 8
    for (int nt = 0; nt < NT2; nt++)
        s += g_part[(size_t)nt * (MDIM * CDIM) + base + tid];
    __shared__ float L[32 * CDIM];
    L[tid] = s;
    __syncthreads();
    const int rl = tid / CDIM;
    float m = -INFINITY;
#pragma unroll
    for (int c = 0; c < CDIM; c++) m = fmaxf(m, L[rl * CDIM + c]);
    float se = 0.0f;
#pragma unroll
    for (int c = 0; c < CDIM; c++) se += expf(L[rl * CDIM + c] - m);
    out[base + tid] = s - m - logf(se);
}

// ---------------- launch ----------------
extern "C" void kernel_launch(void* const* d_in, const int* in_sizes, int n_in,
                              void* d_out, int out_size) {
    const float* x  = (const float*)d_in[0];
    const float* w1 = (const float*)d_in[1];
    const float* s1 = (const float*)d_in[2];
    const float* w2 = (const float*)d_in[3];
    const float* s2 = (const float*)d_in[4];
    float* out = (float*)d_out;

    cudaFuncSetAttribute(k_gemm1, cudaFuncAttributeMaxDynamicSharedMemorySize, SMEM_TOTAL);

    // launch order is load-bearing: ncu captures launch index 3 -> k_gemm1.
    k_select<<<SEL_NB, 256>>>(s1, NK1, J1, 0);                       // 0
    k_select2_w2m<<<1, 1024>>>(s2, w2, NK2, J2);                     // 1
    k_prep<<<W1_BLOCKS + XH_BLOCKS, 256>>>(w1, s1, x);               // 2
    dim3 grid(NT2, MDIM / BM);   // (32, 128)
    k_gemm1<<<grid, GTHREADS, SMEM_TOTAL>>>();                       // 3  <- ncu target
    k_reduce<<<MDIM / 32, 32 * CDIM>>>(out);                         // 4
}

// round 13
// speedup vs baseline: 1.1220x; 1.1040x over previous
#include <cuda_runtime.h>
#include <cuda_fp16.h>
#include <math.h>
#include <stdint.h>

// Problem dims
#define MDIM  16384
#define KDIM  784                  // exact: 12 full K64 stages + 1 K16 stage
#define NDIM  8192
#define CDIM  10
#define NK1   (NDIM * KDIM)
#define NK2   (CDIM * NDIM)
#define J1    3211264u
#define J2    40960u

// GEMM tiling: CTA 128x128, 256 threads, 8 warps as 2(M)x4(N), warp tile 64x32,
// fp32 acc, 3-stage pipeline, 106KB smem -> 2 CTAs per SM (the occupancy fix).
#define BM 128
#define BN 128
#define NT2 (NDIM / BN)            // 64
#define GTHREADS 256
#define ROWB 1568                  // KDIM * 2 bytes
#define ROW32 50176                // 32 * ROWB

// smem layout (3 stages x (16KB A + 16KB B))
#define OFF_A 0                                   // 3 x 16384
#define OFF_B (3 * 16384)                         // 3 x 16384
#define OFF_W2 (OFF_B + 3 * 16384)                // 98304
#define OFF_PART (OFF_W2 + CDIM * BN * 4)         // 103424
#define SMEM_TOTAL (OFF_PART + BM * CDIM * 4)     // 108544 (106KB)

#define SEL_NB 592
#define CAND_MAX 32768
#define W1_BLOCKS (NDIM * (KDIM / 4) / 256)       // 6272
#define XH_BLOCKS (MDIM * (KDIM / 8) / 256)       // 6272

// ---------------- scratch ----------------
__device__ __half   g_xh[MDIM * KDIM];
__device__ __half   g_w1h[NDIM * KDIM];
__device__ float    g_w2m[CDIM * NDIM];
__device__ float    g_part[NT2 * MDIM * CDIM];
__device__ unsigned g_h1024[1024];
__device__ unsigned g_prefix;
__device__ unsigned g_rank;
__device__ unsigned g_nCand;
__device__ unsigned g_T[2];
__device__ unsigned g_cutoff[2];
__device__ unsigned g_candIdx[CAND_MAX];
__device__ unsigned g_candBits[CAND_MAX];
__device__ unsigned g_bar_cnt;
__device__ unsigned g_bar_gen;

__device__ __forceinline__ unsigned fbits_abs(float v) {
    return __float_as_uint(fabsf(v));
}
__device__ __forceinline__ uint32_t smem_u32(const void* p) {
    uint32_t a;
    asm("{ .reg .u64 t; cvta.to.shared.u64 t, %1; cvt.u32.u64 %0, t; }" : "=r"(a) : "l"(p));
    return a;
}

// ---------------- software grid barrier ----------------
__device__ __forceinline__ void grid_bar() {
    __syncthreads();
    if (threadIdx.x == 0) {
        unsigned gen = *((volatile unsigned*)&g_bar_gen);
        __threadfence();
        unsigned a = atomicAdd(&g_bar_cnt, 1u);
        if (a == SEL_NB - 1) {
            g_bar_cnt = 0;
            __threadfence();
            atomicAdd(&g_bar_gen, 1u);
        } else {
            while (*((volatile unsigned*)&g_bar_gen) == gen) { }
        }
        __threadfence();
    }
    __syncthreads();
}

// ---------------- persistent exact radix select for s1: 3 scans total ----------------
__global__ void __launch_bounds__(256) k_select(const float* __restrict__ s, int n,
                                                unsigned j, int sel) {
    __shared__ unsigned h[1024];
    __shared__ unsigned sc[256];
    const int tid = threadIdx.x;
    const int gstride = SEL_NB * 256;
    const int gbase = blockIdx.x * 256 + tid;
    const float4* s4 = (const float4*)s;
    const int n4 = n >> 2;

    if (blockIdx.x == 0) {
        for (int b = tid; b < 1024; b += 256) g_h1024[b] = 0u;
        if (tid == 0) { g_prefix = 0u; g_rank = j; g_nCand = 0u; }
    }
    grid_bar();

#pragma unroll 1
    for (int pass = 0; pass < 3; pass++) {
        const int shift = 20 - 10 * pass;
        const unsigned prefix = g_prefix;
        for (int b = tid; b < 1024; b += 256) h[b] = 0u;
        __syncthreads();
        for (int i = gbase; i < n4; i += gstride) {
            float4 v = s4[i];
            unsigned bb[4];
            bb[0] = fbits_abs(v.x); bb[1] = fbits_abs(v.y);
            bb[2] = fbits_abs(v.z); bb[3] = fbits_abs(v.w);
            if (pass == 0) {
                atomicAdd(&h[bb[0] >> 20], 1u); atomicAdd(&h[bb[1] >> 20], 1u);
                atomicAdd(&h[bb[2] >> 20], 1u); atomicAdd(&h[bb[3] >> 20], 1u);
            } else if (pass == 1) {
#pragma unroll
                for (int c = 0; c < 4; c++)
                    if (((bb[c] ^ prefix) >> 20) == 0u)
                        atomicAdd(&h[(bb[c] >> 10) & 1023u], 1u);
            } else {
#pragma unroll
                for (int c = 0; c < 4; c++) {
                    if (((bb[c] ^ prefix) >> 10) == 0u) {
                        atomicAdd(&h[bb[c] & 1023u], 1u);
                        unsigned p = atomicAdd(&g_nCand, 1u);
                        if (p < CAND_MAX) {
                            g_candIdx[p] = (unsigned)(4 * i + c);
                            g_candBits[p] = bb[c];
                        }
                    }
                }
            }
        }
        __syncthreads();
        for (int b = tid; b < 1024; b += 256)
            if (h[b]) atomicAdd(&g_h1024[b], h[b]);
        grid_bar();

        if (blockIdx.x == 0) {
            unsigned c0 = g_h1024[4 * tid + 0], c1 = g_h1024[4 * tid + 1];
            unsigned c2 = g_h1024[4 * tid + 2], c3 = g_h1024[4 * tid + 3];
            unsigned mysum = c0 + c1 + c2 + c3;
            sc[tid] = mysum;
            __syncthreads();
#pragma unroll
            for (int off = 1; off < 256; off <<= 1) {
                unsigned v = (tid >= off) ? sc[tid - off] : 0u;
                __syncthreads();
                sc[tid] += v;
                __syncthreads();
            }
            unsigned incl = sc[tid], excl = incl - mysum;
            unsigned r = g_rank;
            if (excl <= r && r < incl) {
                unsigned d, cum = excl;
                if (r < cum + c0) { d = 4 * tid + 0; }
                else if (r < cum + c0 + c1) { d = 4 * tid + 1; cum += c0; }
                else if (r < cum + c0 + c1 + c2) { d = 4 * tid + 2; cum += c0 + c1; }
                else { d = 4 * tid + 3; cum += c0 + c1 + c2; }
                g_prefix = g_prefix | (d << shift);
                g_rank = r - cum;
            }
            __syncthreads();
            for (int b = tid; b < 1024; b += 256) g_h1024[b] = 0u;
            __threadfence();
        }
        grid_bar();
    }

    if (blockIdx.x == 0) {
        const unsigned T = g_prefix;
        const unsigned r2 = g_rank;
        if (tid == 0) { g_T[sel] = T; g_cutoff[sel] = 0xFFFFFFFFu; }
        __syncthreads();
        unsigned nc = g_nCand; if (nc > CAND_MAX) nc = CAND_MAX;
        for (unsigned t = tid; t < nc; t += 256u) {
            if (g_candBits[t] == T) {
                unsigned mi = g_candIdx[t];
                unsigned cnt = 0;
                for (unsigned u = 0; u < nc; u++)
                    cnt += (g_candBits[u] == T && g_candIdx[u] < mi) ? 1u : 0u;
                if (cnt == r2) g_cutoff[sel] = mi;
            }
        }
    }
}

// ---------------- single-block select for s2 + fused w2 mask build ----------------
__global__ void __launch_bounds__(1024) k_select2_w2m(const float* __restrict__ s,
                                                      const float* __restrict__ w2,
                                                      int n, unsigned j) {
    __shared__ unsigned h[1024];
    __shared__ unsigned sc[1024];
    __shared__ unsigned tie[4096];
    __shared__ unsigned sPrefix, sRank, sNTie, sNLess, sCut;
    const int tid = threadIdx.x;
    const float4* s4 = (const float4*)s;
    const int n4 = n >> 2;

    if (tid == 0) { sPrefix = 0u; sRank = j; sNTie = 0u; sNLess = 0u; sCut = 0xFFFFFFFFu; }
    __syncthreads();

#pragma unroll 1
    for (int pass = 0; pass < 3; pass++) {
        const int shift = 20 - 10 * pass;
        const unsigned prefix = sPrefix;
        h[tid] = 0u;
        __syncthreads();
        for (int i = tid; i < n4; i += 1024) {
            float4 v = s4[i];
            unsigned b0 = fbits_abs(v.x), b1 = fbits_abs(v.y);
            unsigned b2 = fbits_abs(v.z), b3 = fbits_abs(v.w);
            if (pass == 0) {
                atomicAdd(&h[b0 >> 20], 1u); atomicAdd(&h[b1 >> 20], 1u);
                atomicAdd(&h[b2 >> 20], 1u); atomicAdd(&h[b3 >> 20], 1u);
            } else {
                if (((b0 ^ prefix) >> (shift + 10)) == 0u) atomicAdd(&h[(b0 >> shift) & 1023u], 1u);
                if (((b1 ^ prefix) >> (shift + 10)) == 0u) atomicAdd(&h[(b1 >> shift) & 1023u], 1u);
                if (((b2 ^ prefix) >> (shift + 10)) == 0u) atomicAdd(&h[(b2 >> shift) & 1023u], 1u);
                if (((b3 ^ prefix) >> (shift + 10)) == 0u) atomicAdd(&h[(b3 >> shift) & 1023u], 1u);
            }
        }
        __syncthreads();
        unsigned mine = h[tid];
        sc[tid] = mine;
        __syncthreads();
#pragma unroll
        for (int off = 1; off < 1024; off <<= 1) {
            unsigned v = (tid >= off) ? sc[tid - off] : 0u;
            __syncthreads();
            sc[tid] += v;
            __syncthreads();
        }
        unsigned incl = sc[tid], excl = incl - mine;
        unsigned r = sRank;
        __syncthreads();
        if (excl <= r && r < incl) {
            sPrefix = prefix | ((unsigned)tid << shift);
            sRank = r - excl;
        }
        __syncthreads();
    }

    const unsigned T = sPrefix;
    unsigned nless = 0u;
    for (int i = tid; i < n; i += 1024) {
        unsigned bits = fbits_abs(s[i]);
        if (bits < T) nless++;
        else if (bits == T) {
            unsigned p = atomicAdd(&sNTie, 1u);
            if (p < 4096u) tie[p] = (unsigned)i;
        }
    }
    sc[tid] = nless;
    __syncthreads();
#pragma unroll
    for (int off = 512; off > 0; off >>= 1) {
        if (tid < off) sc[tid] += sc[tid + off];
        __syncthreads();
    }
    if (tid == 0) sNLess = sc[0];
    __syncthreads();

    {
        unsigned nTie = sNTie; if (nTie > 4096u) nTie = 4096u;
        unsigned r2 = j - sNLess;
        if (r2 < nTie) {
            for (unsigned t = tid; t < nTie; t += 1024u) {
                unsigned mi = tie[t];
                unsigned cnt = 0;
                for (unsigned u = 0; u < nTie; u++) cnt += (tie[u] < mi) ? 1u : 0u;
                if (cnt == r2) sCut = mi;
            }
        }
    }
    __syncthreads();
    const unsigned cut = sCut;
    if (tid == 0) { g_T[1] = T; g_cutoff[1] = cut; }

    for (int i = tid; i < n; i += 1024) {
        unsigned bits = fbits_abs(s[i]);
        bool keep = (bits > T) || (bits == T && (unsigned)i >= cut);
        g_w2m[i] = keep ? w2[i] : 0.0f;
    }
}

// ---------------- fused prep: masked fp16 w1 + fp16 x (K = 784 exactly) ----------------
__global__ void __launch_bounds__(256) k_prep(const float* __restrict__ w1,
                                              const float* __restrict__ s1,
                                              const float* __restrict__ x) {
    const int b = blockIdx.x;
    const int tid = threadIdx.x;
    if (b < W1_BLOCKS) {
        int i = b * 256 + tid;
        int src = i * 4;
        float4 w = *(const float4*)(w1 + src);
        float4 sv = *(const float4*)(s1 + src);
        unsigned T = g_T[0], cut = g_cutoff[0];
        unsigned b0 = fbits_abs(sv.x), b1 = fbits_abs(sv.y);
        unsigned b2 = fbits_abs(sv.z), b3 = fbits_abs(sv.w);
        float f0 = ((b0 > T) || (b0 == T && (unsigned)(src + 0) >= cut)) ? w.x : 0.0f;
        float f1 = ((b1 > T) || (b1 == T && (unsigned)(src + 1) >= cut)) ? w.y : 0.0f;
        float f2 = ((b2 > T) || (b2 == T && (unsigned)(src + 2) >= cut)) ? w.z : 0.0f;
        float f3 = ((b3 > T) || (b3 == T && (unsigned)(src + 3) >= cut)) ? w.w : 0.0f;
        __half2 o[2];
        o[0] = __floats2half2_rn(f0, f1);
        o[1] = __floats2half2_rn(f2, f3);
        *(uint2*)(g_w1h + src) = *(const uint2*)o;
    } else {
        int i = (b - W1_BLOCKS) * 256 + tid;
        int src = i * 8;
        const float4* p = (const float4*)(x + src);
        float4 v0 = p[0], v1 = p[1];
        __half2 h[4];
        h[0] = __floats2half2_rn(v0.x, v0.y);
        h[1] = __floats2half2_rn(v0.z, v0.w);
        h[2] = __floats2half2_rn(v1.x, v1.y);
        h[3] = __floats2half2_rn(v1.z, v1.w);
        *(uint4*)(g_xh + src) = *(const uint4*)h;
    }
}

// ---------------- GEMM helpers (immediate-offset addressing) ----------------
#define CP_COMMIT() asm volatile("cp.async.commit_group;" ::: "memory")
#define CP_WAIT(n)  asm volatile("cp.async.wait_group %0;" :: "n"(n) : "memory")

#define CP16_O(SREG, SOFS, GREG, GOFS) \
    asm volatile("cp.async.cg.shared.global [%0+" SOFS "], [%1+" GOFS "], 16;" \
                 :: "r"(SREG), "l"(GREG))

#define LDSM4_O(R0, R1, R2, R3, BASE, OFS) \
    asm volatile("ldmatrix.sync.aligned.m8n8.x4.shared.b16 {%0,%1,%2,%3}, [%4+" OFS "];" \
                 : "=r"(R0), "=r"(R1), "=r"(R2), "=r"(R3) : "r"(BASE))

__device__ __forceinline__ void mma_fp16(float* d, const unsigned* a, const unsigned* b) {
    asm volatile(
        "mma.sync.aligned.m16n8k16.row.col.f32.f16.f16.f32 "
        "{%0,%1,%2,%3}, {%4,%5,%6,%7}, {%8,%9}, {%0,%1,%2,%3};\n"
        : "+f"(d[0]), "+f"(d[1]), "+f"(d[2]), "+f"(d[3])
        : "r"(a[0]), "r"(a[1]), "r"(a[2]), "r"(a[3]), "r"(b[0]), "r"(b[1]));
}

__device__ __forceinline__ uint32_t sw_off(uint32_t row, uint32_t u) {
    return row * 128u + ((u ^ (row & 7u)) << 4);
}

// ---------------- GEMM1: 128x128 CTA, 2 CTAs/SM, fp32 acc, K=784 exact ----------------
__global__ void __launch_bounds__(GTHREADS, 2) k_gemm1() {
    extern __shared__ __align__(1024) char smem[];
    const uint32_t sb = smem_u32(smem);
    const int tid = threadIdx.x;
    const int nt = blockIdx.x;   // 0..63
    const int mt = blockIdx.y;   // 0..127

    const int wid = tid >> 5, lane = tid & 31;
    const int mw = wid & 1;      // 2 M warp-blocks of 64
    const int nw = wid >> 1;     // 4 N warp-blocks of 32
    const int g4 = lane >> 2, t4 = lane & 3;
    const int r8 = lane & 7;

    float* W2s  = (float*)(smem + OFF_W2);
    float* Part = (float*)(smem + OFF_PART);
    for (int p = tid; p < CDIM * BN; p += GTHREADS)
        W2s[p] = g_w2m[(p >> 7) * NDIM + nt * BN + (p & 127)];
    for (int p = tid; p < BM * CDIM; p += GTHREADS)
        Part[p] = 0.0f;

    const char* aG0 = (const char*)(g_xh  + (size_t)(mt * BM) * KDIM)
                      + (size_t)(tid >> 3) * ROWB + (tid & 7) * 16;
    const char* bG0 = (const char*)(g_w1h + (size_t)(nt * BN) * KDIM)
                      + (size_t)(tid >> 3) * ROWB + (tid & 7) * 16;
    const uint32_t sA0 = sb + OFF_A + sw_off((uint32_t)(tid >> 3), (uint32_t)(tid & 7));
    const uint32_t sB0 = sb + OFF_B + sw_off((uint32_t)(tid >> 3), (uint32_t)(tid & 7));

    const uint32_t aRowL = (uint32_t)(mw * 64 + ((lane >> 3) & 1) * 8 + r8);
    const uint32_t uA    = (uint32_t)(lane >> 4);
    const uint32_t bRowL = (uint32_t)(nw * 32 + (lane >> 4) * 8 + r8);
    const uint32_t uB    = (uint32_t)((lane >> 3) & 1);

    float d[4][4][4];
#pragma unroll
    for (int i = 0; i < 4; i++)
#pragma unroll
        for (int j = 0; j < 4; j++)
#pragma unroll
            for (int r = 0; r < 4; r++) d[i][j][r] = 0.0f;

// slot = st % 3. A: 4 cp16, B: 4 cp16 (both 16KB/stage, 32-row groups).
#define ISSUE_STAGE(st) do {                                                      \
    const int _sl = (st) % 3;                                                     \
    const uint32_t _sA = sA0 + _sl * 16384;                                       \
    const char*    _gA = aG0 + (size_t)(st) * 128;                                \
    CP16_O(_sA, "0",     _gA, "0");                                               \
    CP16_O(_sA, "4096",  _gA, "50176");                                           \
    CP16_O(_sA, "8192",  _gA, "100352");                                          \
    CP16_O(_sA, "12288", _gA, "150528");                                          \
    const uint32_t _sB = sB0 + _sl * 16384;                                       \
    const char*    _gB = bG0 + (size_t)(st) * 128;                                \
    CP16_O(_sB, "0",     _gB, "0");                                               \
    CP16_O(_sB, "4096",  _gB, "50176");                                           \
    CP16_O(_sB, "8192",  _gB, "100352");                                          \
    CP16_O(_sB, "12288", _gB, "150528");                                          \
} while (0)

#define COMPUTE_KS(_aB, _bB, ksv) do {                                            \
    const uint32_t _ul = (uint32_t)(2 * (ksv));                                   \
    unsigned A4[4][4], B4[2][4];                                                  \
    const uint32_t _aAd = (_aB) + sw_off(aRowL, _ul + uA);                        \
    LDSM4_O(A4[0][0], A4[0][1], A4[0][2], A4[0][3], _aAd, "0");                   \
    LDSM4_O(A4[1][0], A4[1][1], A4[1][2], A4[1][3], _aAd, "2048");                \
    LDSM4_O(A4[2][0], A4[2][1], A4[2][2], A4[2][3], _aAd, "4096");                \
    LDSM4_O(A4[3][0], A4[3][1], A4[3][2], A4[3][3], _aAd, "6144");                \
    const uint32_t _bAd = (_bB) + sw_off(bRowL, _ul + uB);                        \
    LDSM4_O(B4[0][0], B4[0][1], B4[0][2], B4[0][3], _bAd, "0");                   \
    LDSM4_O(B4[1][0], B4[1][1], B4[1][2], B4[1][3], _bAd, "2048");                \
    _Pragma("unroll")                                                             \
    for (int i = 0; i < 4; i++)                                                   \
        _Pragma("unroll")                                                         \
        for (int j = 0; j < 4; j++)                                               \
            mma_fp16(d[i][j], A4[i], &B4[j >> 1][2 * (j & 1)]);                   \
} while (0)

#define COMPUTE_STAGE(kk) do {                                                    \
    const uint32_t _aB = sb + OFF_A + ((kk) % 3) * 16384;                         \
    const uint32_t _bB = sb + OFF_B + ((kk) % 3) * 16384;                         \
    COMPUTE_KS(_aB, _bB, 0);                                                      \
    COMPUTE_KS(_aB, _bB, 1);                                                      \
    COMPUTE_KS(_aB, _bB, 2);                                                      \
    COMPUTE_KS(_aB, _bB, 3);                                                      \
} while (0)

    ISSUE_STAGE(0); CP_COMMIT();
    ISSUE_STAGE(1); CP_COMMIT();

    // stages 0..9: compute kk, issue kk+2 (stages 2..11)
#pragma unroll 1
    for (int kk = 0; kk < 10; kk++) {
        CP_WAIT(1);
        __syncthreads();
        ISSUE_STAGE(kk + 2);
        CP_COMMIT();
        COMPUTE_STAGE(kk);
    }
    // stage 10: issue partial stage 12 (K16 tail: only units 0,1)
    CP_WAIT(1);
    __syncthreads();
    if ((tid & 7) < 2) ISSUE_STAGE(12);
    CP_COMMIT();
    COMPUTE_STAGE(10);
    // stage 11
    CP_WAIT(1);
    __syncthreads();
    CP_COMMIT();
    COMPUTE_STAGE(11);
    // stage 12: K16 only (slot 0, ks=0)
    CP_WAIT(0);
    __syncthreads();
    {
        const uint32_t _aB = sb + OFF_A + 0 * 16384;
        const uint32_t _bB = sb + OFF_B + 0 * 16384;
        COMPUTE_KS(_aB, _bB, 0);
    }

    // ---- epilogue: relu + contract with w2 slice ----
#pragma unroll
    for (int i = 0; i < 4; i++) {
#pragma unroll
        for (int h = 0; h < 2; h++) {
            const int row = mw * 64 + i * 16 + g4 + h * 8;
            float v0[4], v1[4];
#pragma unroll
            for (int j = 0; j < 4; j++) {
                v0[j] = fmaxf(d[i][j][2 * h + 0], 0.0f);
                v1[j] = fmaxf(d[i][j][2 * h + 1], 0.0f);
            }
#pragma unroll
            for (int c = 0; c < CDIM; c++) {
                float s = 0.0f;
#pragma unroll
                for (int j = 0; j < 4; j++) {
                    float2 w = *(const float2*)&W2s[c * BN + nw * 32 + j * 8 + 2 * t4];
                    s += v0[j] * w.x + v1[j] * w.y;
                }
                s += __shfl_xor_sync(0xFFFFFFFFu, s, 1);
                s += __shfl_xor_sync(0xFFFFFFFFu, s, 2);
                if (t4 == 0) atomicAdd(&Part[row * CDIM + c], s);
            }
        }
    }
    __syncthreads();

    float* outp = g_part + (size_t)nt * (MDIM * CDIM) + (size_t)(mt * BM) * CDIM;
    for (int p = tid; p < BM * CDIM; p += GTHREADS) outp[p] = Part[p];
#undef COMPUTE_STAGE
#undef COMPUTE_KS
#undef ISSUE_STAGE
}

// ---------------- reduce partials + log_softmax ----------------
__global__ void k_reduce(float* __restrict__ out) {   // <<<512, 320>>>
    const int tid = threadIdx.x;
    const int base = blockIdx.x * 32 * CDIM;
    float s = 0.0f;
#pragma unroll 8
    for (int nt = 0; nt < NT2; nt++)
        s += g_part[(size_t)nt * (MDIM * CDIM) + base + tid];
    __shared__ float L[32 * CDIM];
    L[tid] = s;
    __syncthreads();
    const int rl = tid / CDIM;
    float m = -INFINITY;
#pragma unroll
    for (int c = 0; c < CDIM; c++) m = fmaxf(m, L[rl * CDIM + c]);
    float se = 0.0f;
#pragma unroll
    for (int c = 0; c < CDIM; c++) se += expf(L[rl * CDIM + c] - m);
    out[base + tid] = s - m - logf(se);
}

// ---------------- launch ----------------
extern "C" void kernel_launch(void* const* d_in, const int* in_sizes, int n_in,
                              void* d_out, int out_size) {
    const float* x  = (const float*)d_in[0];
    const float* w1 = (const float*)d_in[1];
    const float* s1 = (const float*)d_in[2];
    const float* w2 = (const float*)d_in[3];
    const float* s2 = (const float*)d_in[4];
    float* out = (float*)d_out;

    cudaFuncSetAttribute(k_gemm1, cudaFuncAttributeMaxDynamicSharedMemorySize, SMEM_TOTAL);

    // launch order is load-bearing: ncu captures launch index 3 -> k_gemm1.
    k_select<<<SEL_NB, 256>>>(s1, NK1, J1, 0);                       // 0
    k_select2_w2m<<<1, 1024>>>(s2, w2, NK2, J2);                     // 1
    k_prep<<<W1_BLOCKS + XH_BLOCKS, 256>>>(w1, s1, x);               // 2
    dim3 grid(NT2, MDIM / BM);   // (64, 128)
    k_gemm1<<<grid, GTHREADS, SMEM_TOTAL>>>();                       // 3  <- ncu target
    k_reduce<<<MDIM / 32, 32 * CDIM>>>(out);                         // 4
}

// round 14
// speedup vs baseline: 1.1267x; 1.0042x over previous
#include <cuda_runtime.h>
#include <cuda_fp16.h>
#include <math.h>
#include <stdint.h>

// Problem dims
#define MDIM  16384
#define KDIM  784                  // exact: 12 full K64 stages + 1 K16 stage
#define NDIM  8192
#define CDIM  10
#define NK1   (NDIM * KDIM)
#define NK2   (CDIM * NDIM)
#define J1    3211264u
#define J2    40960u

// GEMM tiling: CTA 128x128, 256 threads, 8 warps as 2(M)x4(N), warp tile 64x32,
// split-K fp16 accumulation (even stages->dh_a, odd->dh_b), 3-stage pipeline,
// 106KB smem -> 2 CTAs per SM.
#define BM 128
#define BN 128
#define NT2 (NDIM / BN)            // 64
#define GTHREADS 256
#define ROWB 1568                  // KDIM * 2 bytes

// smem layout (3 stages x (16KB A + 16KB B))
#define OFF_A 0
#define OFF_B (3 * 16384)
#define OFF_W2 (OFF_B + 3 * 16384)                // 98304
#define OFF_PART (OFF_W2 + CDIM * BN * 4)         // 103424
#define SMEM_TOTAL (OFF_PART + BM * CDIM * 4)     // 108544

#define SEL_NB 592
#define CAND_MAX 32768
#define W1_BLOCKS (NDIM * (KDIM / 4) / 256)       // 6272
#define XH_BLOCKS (MDIM * (KDIM / 8) / 256)       // 6272

// ---------------- scratch ----------------
__device__ __half   g_xh[MDIM * KDIM];
__device__ __half   g_w1h[NDIM * KDIM];
__device__ float    g_w2m[CDIM * NDIM];
__device__ float    g_part[NT2 * MDIM * CDIM];
__device__ unsigned g_h1024[1024];
__device__ unsigned g_prefix;
__device__ unsigned g_rank;
__device__ unsigned g_nCand;
__device__ unsigned g_T[2];
__device__ unsigned g_cutoff[2];
__device__ unsigned g_candIdx[CAND_MAX];
__device__ unsigned g_candBits[CAND_MAX];
__device__ unsigned g_bar_cnt;
__device__ unsigned g_bar_gen;

__device__ __forceinline__ unsigned fbits_abs(float v) {
    return __float_as_uint(fabsf(v));
}
__device__ __forceinline__ uint32_t smem_u32(const void* p) {
    uint32_t a;
    asm("{ .reg .u64 t; cvta.to.shared.u64 t, %1; cvt.u32.u64 %0, t; }" : "=r"(a) : "l"(p));
    return a;
}

// ---------------- software grid barrier ----------------
__device__ __forceinline__ void grid_bar() {
    __syncthreads();
    if (threadIdx.x == 0) {
        unsigned gen = *((volatile unsigned*)&g_bar_gen);
        __threadfence();
        unsigned a = atomicAdd(&g_bar_cnt, 1u);
        if (a == SEL_NB - 1) {
            g_bar_cnt = 0;
            __threadfence();
            atomicAdd(&g_bar_gen, 1u);
        } else {
            while (*((volatile unsigned*)&g_bar_gen) == gen) { }
        }
        __threadfence();
    }
    __syncthreads();
}

// ---------------- persistent exact radix select for s1: 3 scans total ----------------
__global__ void __launch_bounds__(256) k_select(const float* __restrict__ s, int n,
                                                unsigned j, int sel) {
    __shared__ unsigned h[1024];
    __shared__ unsigned sc[256];
    const int tid = threadIdx.x;
    const int gstride = SEL_NB * 256;
    const int gbase = blockIdx.x * 256 + tid;
    const float4* s4 = (const float4*)s;
    const int n4 = n >> 2;

    if (blockIdx.x == 0) {
        for (int b = tid; b < 1024; b += 256) g_h1024[b] = 0u;
        if (tid == 0) { g_prefix = 0u; g_rank = j; g_nCand = 0u; }
    }
    grid_bar();

#pragma unroll 1
    for (int pass = 0; pass < 3; pass++) {
        const int shift = 20 - 10 * pass;
        const unsigned prefix = g_prefix;
        for (int b = tid; b < 1024; b += 256) h[b] = 0u;
        __syncthreads();
        for (int i = gbase; i < n4; i += gstride) {
            float4 v = s4[i];
            unsigned bb[4];
            bb[0] = fbits_abs(v.x); bb[1] = fbits_abs(v.y);
            bb[2] = fbits_abs(v.z); bb[3] = fbits_abs(v.w);
            if (pass == 0) {
                atomicAdd(&h[bb[0] >> 20], 1u); atomicAdd(&h[bb[1] >> 20], 1u);
                atomicAdd(&h[bb[2] >> 20], 1u); atomicAdd(&h[bb[3] >> 20], 1u);
            } else if (pass == 1) {
#pragma unroll
                for (int c = 0; c < 4; c++)
                    if (((bb[c] ^ prefix) >> 20) == 0u)
                        atomicAdd(&h[(bb[c] >> 10) & 1023u], 1u);
            } else {
#pragma unroll
                for (int c = 0; c < 4; c++) {
                    if (((bb[c] ^ prefix) >> 10) == 0u) {
                        atomicAdd(&h[bb[c] & 1023u], 1u);
                        unsigned p = atomicAdd(&g_nCand, 1u);
                        if (p < CAND_MAX) {
                            g_candIdx[p] = (unsigned)(4 * i + c);
                            g_candBits[p] = bb[c];
                        }
                    }
                }
            }
        }
        __syncthreads();
        for (int b = tid; b < 1024; b += 256)
            if (h[b]) atomicAdd(&g_h1024[b], h[b]);
        grid_bar();

        if (blockIdx.x == 0) {
            unsigned c0 = g_h1024[4 * tid + 0], c1 = g_h1024[4 * tid + 1];
            unsigned c2 = g_h1024[4 * tid + 2], c3 = g_h1024[4 * tid + 3];
            unsigned mysum = c0 + c1 + c2 + c3;
            sc[tid] = mysum;
            __syncthreads();
#pragma unroll
            for (int off = 1; off < 256; off <<= 1) {
                unsigned v = (tid >= off) ? sc[tid - off] : 0u;
                __syncthreads();
                sc[tid] += v;
                __syncthreads();
            }
            unsigned incl = sc[tid], excl = incl - mysum;
            unsigned r = g_rank;
            if (excl <= r && r < incl) {
                unsigned d, cum = excl;
                if (r < cum + c0) { d = 4 * tid + 0; }
                else if (r < cum + c0 + c1) { d = 4 * tid + 1; cum += c0; }
                else if (r < cum + c0 + c1 + c2) { d = 4 * tid + 2; cum += c0 + c1; }
                else { d = 4 * tid + 3; cum += c0 + c1 + c2; }
                g_prefix = g_prefix | (d << shift);
                g_rank = r - cum;
            }
            __syncthreads();
            for (int b = tid; b < 1024; b += 256) g_h1024[b] = 0u;
            __threadfence();
        }
        grid_bar();
    }

    if (blockIdx.x == 0) {
        const unsigned T = g_prefix;
        const unsigned r2 = g_rank;
        if (tid == 0) { g_T[sel] = T; g_cutoff[sel] = 0xFFFFFFFFu; }
        __syncthreads();
        unsigned nc = g_nCand; if (nc > CAND_MAX) nc = CAND_MAX;
        for (unsigned t = tid; t < nc; t += 256u) {
            if (g_candBits[t] == T) {
                unsigned mi = g_candIdx[t];
                unsigned cnt = 0;
                for (unsigned u = 0; u < nc; u++)
                    cnt += (g_candBits[u] == T && g_candIdx[u] < mi) ? 1u : 0u;
                if (cnt == r2) g_cutoff[sel] = mi;
            }
        }
    }
}

// ---------------- single-block select for s2 + fused w2 mask build ----------------
__global__ void __launch_bounds__(1024) k_select2_w2m(const float* __restrict__ s,
                                                      const float* __restrict__ w2,
                                                      int n, unsigned j) {
    __shared__ unsigned h[1024];
    __shared__ unsigned sc[1024];
    __shared__ unsigned tie[4096];
    __shared__ unsigned sPrefix, sRank, sNTie, sNLess, sCut;
    const int tid = threadIdx.x;
    const float4* s4 = (const float4*)s;
    const int n4 = n >> 2;

    if (tid == 0) { sPrefix = 0u; sRank = j; sNTie = 0u; sNLess = 0u; sCut = 0xFFFFFFFFu; }
    __syncthreads();

#pragma unroll 1
    for (int pass = 0; pass < 3; pass++) {
        const int shift = 20 - 10 * pass;
        const unsigned prefix = sPrefix;
        h[tid] = 0u;
        __syncthreads();
        for (int i = tid; i < n4; i += 1024) {
            float4 v = s4[i];
            unsigned b0 = fbits_abs(v.x), b1 = fbits_abs(v.y);
            unsigned b2 = fbits_abs(v.z), b3 = fbits_abs(v.w);
            if (pass == 0) {
                atomicAdd(&h[b0 >> 20], 1u); atomicAdd(&h[b1 >> 20], 1u);
                atomicAdd(&h[b2 >> 20], 1u); atomicAdd(&h[b3 >> 20], 1u);
            } else {
                if (((b0 ^ prefix) >> (shift + 10)) == 0u) atomicAdd(&h[(b0 >> shift) & 1023u], 1u);
                if (((b1 ^ prefix) >> (shift + 10)) == 0u) atomicAdd(&h[(b1 >> shift) & 1023u], 1u);
                if (((b2 ^ prefix) >> (shift + 10)) == 0u) atomicAdd(&h[(b2 >> shift) & 1023u], 1u);
                if (((b3 ^ prefix) >> (shift + 10)) == 0u) atomicAdd(&h[(b3 >> shift) & 1023u], 1u);
            }
        }
        __syncthreads();
        unsigned mine = h[tid];
        sc[tid] = mine;
        __syncthreads();
#pragma unroll
        for (int off = 1; off < 1024; off <<= 1) {
            unsigned v = (tid >= off) ? sc[tid - off] : 0u;
            __syncthreads();
            sc[tid] += v;
            __syncthreads();
        }
        unsigned incl = sc[tid], excl = incl - mine;
        unsigned r = sRank;
        __syncthreads();
        if (excl <= r && r < incl) {
            sPrefix = prefix | ((unsigned)tid << shift);
            sRank = r - excl;
        }
        __syncthreads();
    }

    const unsigned T = sPrefix;
    unsigned nless = 0u;
    for (int i = tid; i < n; i += 1024) {
        unsigned bits = fbits_abs(s[i]);
        if (bits < T) nless++;
        else if (bits == T) {
            unsigned p = atomicAdd(&sNTie, 1u);
            if (p < 4096u) tie[p] = (unsigned)i;
        }
    }
    sc[tid] = nless;
    __syncthreads();
#pragma unroll
    for (int off = 512; off > 0; off >>= 1) {
        if (tid < off) sc[tid] += sc[tid + off];
        __syncthreads();
    }
    if (tid == 0) sNLess = sc[0];
    __syncthreads();

    {
        unsigned nTie = sNTie; if (nTie > 4096u) nTie = 4096u;
        unsigned r2 = j - sNLess;
        if (r2 < nTie) {
            for (unsigned t = tid; t < nTie; t += 1024u) {
                unsigned mi = tie[t];
                unsigned cnt = 0;
                for (unsigned u = 0; u < nTie; u++) cnt += (tie[u] < mi) ? 1u : 0u;
                if (cnt == r2) sCut = mi;
            }
        }
    }
    __syncthreads();
    const unsigned cut = sCut;
    if (tid == 0) { g_T[1] = T; g_cutoff[1] = cut; }

    for (int i = tid; i < n; i += 1024) {
        unsigned bits = fbits_abs(s[i]);
        bool keep = (bits > T) || (bits == T && (unsigned)i >= cut);
        g_w2m[i] = keep ? w2[i] : 0.0f;
    }
}

// ---------------- fused prep: masked fp16 w1 + fp16 x (K = 784 exactly) ----------------
__global__ void __launch_bounds__(256) k_prep(const float* __restrict__ w1,
                                              const float* __restrict__ s1,
                                              const float* __restrict__ x) {
    const int b = blockIdx.x;
    const int tid = threadIdx.x;
    if (b < W1_BLOCKS) {
        int i = b * 256 + tid;
        int src = i * 4;
        float4 w = *(const float4*)(w1 + src);
        float4 sv = *(const float4*)(s1 + src);
        unsigned T = g_T[0], cut = g_cutoff[0];
        unsigned b0 = fbits_abs(sv.x), b1 = fbits_abs(sv.y);
        unsigned b2 = fbits_abs(sv.z), b3 = fbits_abs(sv.w);
        float f0 = ((b0 > T) || (b0 == T && (unsigned)(src + 0) >= cut)) ? w.x : 0.0f;
        float f1 = ((b1 > T) || (b1 == T && (unsigned)(src + 1) >= cut)) ? w.y : 0.0f;
        float f2 = ((b2 > T) || (b2 == T && (unsigned)(src + 2) >= cut)) ? w.z : 0.0f;
        float f3 = ((b3 > T) || (b3 == T && (unsigned)(src + 3) >= cut)) ? w.w : 0.0f;
        __half2 o[2];
        o[0] = __floats2half2_rn(f0, f1);
        o[1] = __floats2half2_rn(f2, f3);
        *(uint2*)(g_w1h + src) = *(const uint2*)o;
    } else {
        int i = (b - W1_BLOCKS) * 256 + tid;
        int src = i * 8;
        const float4* p = (const float4*)(x + src);
        float4 v0 = p[0], v1 = p[1];
        __half2 h[4];
        h[0] = __floats2half2_rn(v0.x, v0.y);
        h[1] = __floats2half2_rn(v0.z, v0.w);
        h[2] = __floats2half2_rn(v1.x, v1.y);
        h[3] = __floats2half2_rn(v1.z, v1.w);
        *(uint4*)(g_xh + src) = *(const uint4*)h;
    }
}

// ---------------- GEMM helpers (immediate-offset addressing) ----------------
#define CP_COMMIT() asm volatile("cp.async.commit_group;" ::: "memory")
#define CP_WAIT(n)  asm volatile("cp.async.wait_group %0;" :: "n"(n) : "memory")

#define CP16_O(SREG, SOFS, GREG, GOFS) \
    asm volatile("cp.async.cg.shared.global [%0+" SOFS "], [%1+" GOFS "], 16;" \
                 :: "r"(SREG), "l"(GREG))

#define LDSM4_O(R0, R1, R2, R3, BASE, OFS) \
    asm volatile("ldmatrix.sync.aligned.m8n8.x4.shared.b16 {%0,%1,%2,%3}, [%4+" OFS "];" \
                 : "=r"(R0), "=r"(R1), "=r"(R2), "=r"(R3) : "r"(BASE))

// fp16-accumulating MMA: D,C are 2 regs (4 halves)
__device__ __forceinline__ void mma_fp16h(unsigned* d, const unsigned* a, const unsigned* b) {
    asm volatile(
        "mma.sync.aligned.m16n8k16.row.col.f16.f16.f16.f16 "
        "{%0,%1}, {%2,%3,%4,%5}, {%6,%7}, {%0,%1};\n"
        : "+r"(d[0]), "+r"(d[1])
        : "r"(a[0]), "r"(a[1]), "r"(a[2]), "r"(a[3]), "r"(b[0]), "r"(b[1]));
}

__device__ __forceinline__ uint32_t sw_off(uint32_t row, uint32_t u) {
    return row * 128u + ((u ^ (row & 7u)) << 4);
}

// ---------------- GEMM1: 128x128 CTA, 2 CTAs/SM, split-K fp16 acc, K=784 exact ----------------
__global__ void __launch_bounds__(GTHREADS, 2) k_gemm1() {
    extern __shared__ __align__(1024) char smem[];
    const uint32_t sb = smem_u32(smem);
    const int tid = threadIdx.x;
    const int nt = blockIdx.x;   // 0..63
    const int mt = blockIdx.y;   // 0..127

    const int wid = tid >> 5, lane = tid & 31;
    const int mw = wid & 1;      // 2 M warp-blocks of 64
    const int nw = wid >> 1;     // 4 N warp-blocks of 32
    const int g4 = lane >> 2, t4 = lane & 3;
    const int r8 = lane & 7;

    float* W2s  = (float*)(smem + OFF_W2);
    float* Part = (float*)(smem + OFF_PART);
    for (int p = tid; p < CDIM * BN; p += GTHREADS)
        W2s[p] = g_w2m[(p >> 7) * NDIM + nt * BN + (p & 127)];
    for (int p = tid; p < BM * CDIM; p += GTHREADS)
        Part[p] = 0.0f;

    const char* aG0 = (const char*)(g_xh  + (size_t)(mt * BM) * KDIM)
                      + (size_t)(tid >> 3) * ROWB + (tid & 7) * 16;
    const char* bG0 = (const char*)(g_w1h + (size_t)(nt * BN) * KDIM)
                      + (size_t)(tid >> 3) * ROWB + (tid & 7) * 16;
    const uint32_t sA0 = sb + OFF_A + sw_off((uint32_t)(tid >> 3), (uint32_t)(tid & 7));
    const uint32_t sB0 = sb + OFF_B + sw_off((uint32_t)(tid >> 3), (uint32_t)(tid & 7));

    const uint32_t aRowL = (uint32_t)(mw * 64 + ((lane >> 3) & 1) * 8 + r8);
    const uint32_t uA    = (uint32_t)(lane >> 4);
    const uint32_t bRowL = (uint32_t)(nw * 32 + (lane >> 4) * 8 + r8);
    const uint32_t uB    = (uint32_t)((lane >> 3) & 1);

    // split-K fp16 accumulators: even K64 stages -> dh_a, odd -> dh_b (32 regs each)
    unsigned dh_a[4][4][2], dh_b[4][4][2];
#pragma unroll
    for (int i = 0; i < 4; i++)
#pragma unroll
        for (int j = 0; j < 4; j++) {
            dh_a[i][j][0] = 0u; dh_a[i][j][1] = 0u;
            dh_b[i][j][0] = 0u; dh_b[i][j][1] = 0u;
        }

#define ISSUE_STAGE(st) do {                                                      \
    const int _sl = (st) % 3;                                                     \
    const uint32_t _sA = sA0 + _sl * 16384;                                       \
    const char*    _gA = aG0 + (size_t)(st) * 128;                                \
    CP16_O(_sA, "0",     _gA, "0");                                               \
    CP16_O(_sA, "4096",  _gA, "50176");                                           \
    CP16_O(_sA, "8192",  _gA, "100352");                                          \
    CP16_O(_sA, "12288", _gA, "150528");                                          \
    const uint32_t _sB = sB0 + _sl * 16384;                                       \
    const char*    _gB = bG0 + (size_t)(st) * 128;                                \
    CP16_O(_sB, "0",     _gB, "0");                                               \
    CP16_O(_sB, "4096",  _gB, "50176");                                           \
    CP16_O(_sB, "8192",  _gB, "100352");                                          \
    CP16_O(_sB, "12288", _gB, "150528");                                          \
} while (0)

#define COMPUTE_KS(_aB, _bB, ksv, DH) do {                                        \
    const uint32_t _ul = (uint32_t)(2 * (ksv));                                   \
    unsigned A4[4][4], B4[2][4];                                                  \
    const uint32_t _aAd = (_aB) + sw_off(aRowL, _ul + uA);                        \
    LDSM4_O(A4[0][0], A4[0][1], A4[0][2], A4[0][3], _aAd, "0");                   \
    LDSM4_O(A4[1][0], A4[1][1], A4[1][2], A4[1][3], _aAd, "2048");                \
    LDSM4_O(A4[2][0], A4[2][1], A4[2][2], A4[2][3], _aAd, "4096");                \
    LDSM4_O(A4[3][0], A4[3][1], A4[3][2], A4[3][3], _aAd, "6144");                \
    const uint32_t _bAd = (_bB) + sw_off(bRowL, _ul + uB);                        \
    LDSM4_O(B4[0][0], B4[0][1], B4[0][2], B4[0][3], _bAd, "0");                   \
    LDSM4_O(B4[1][0], B4[1][1], B4[1][2], B4[1][3], _bAd, "2048");                \
    _Pragma("unroll")                                                             \
    for (int i = 0; i < 4; i++)                                                   \
        _Pragma("unroll")                                                         \
        for (int j = 0; j < 4; j++)                                               \
            mma_fp16h(DH[i][j], A4[i], &B4[j >> 1][2 * (j & 1)]);                 \
} while (0)

#define COMPUTE_STAGE(kk, DH) do {                                                \
    const uint32_t _aB = sb + OFF_A + ((kk) % 3) * 16384;                         \
    const uint32_t _bB = sb + OFF_B + ((kk) % 3) * 16384;                         \
    COMPUTE_KS(_aB, _bB, 0, DH);                                                  \
    COMPUTE_KS(_aB, _bB, 1, DH);                                                  \
    COMPUTE_KS(_aB, _bB, 2, DH);                                                  \
    COMPUTE_KS(_aB, _bB, 3, DH);                                                  \
} while (0)

#define STAGE_FULL(kk, DH) do {                                                   \
    CP_WAIT(1);                                                                   \
    __syncthreads();                                                              \
    ISSUE_STAGE((kk) + 2);                                                        \
    CP_COMMIT();                                                                  \
    COMPUTE_STAGE(kk, DH);                                                        \
} while (0)

    ISSUE_STAGE(0); CP_COMMIT();
    ISSUE_STAGE(1); CP_COMMIT();

    // stages 0..9 (issues 2..11): even -> dh_a, odd -> dh_b
#pragma unroll 1
    for (int kb = 0; kb < 5; kb++) {
        STAGE_FULL(2 * kb + 0, dh_a);
        STAGE_FULL(2 * kb + 1, dh_b);
    }
    // stage 10 (even -> a): issue partial stage 12 (K16 tail: units 0,1)
    CP_WAIT(1);
    __syncthreads();
    if ((tid & 7) < 2) ISSUE_STAGE(12);
    CP_COMMIT();
    COMPUTE_STAGE(10, dh_a);
    // stage 11 (odd -> b)
    CP_WAIT(1);
    __syncthreads();
    CP_COMMIT();
    COMPUTE_STAGE(11, dh_b);
    // stage 12 (K16 only, slot 0, ks=0 -> a)
    CP_WAIT(0);
    __syncthreads();
    {
        const uint32_t _aB = sb + OFF_A + 0 * 16384;
        const uint32_t _bB = sb + OFF_B + 0 * 16384;
        COMPUTE_KS(_aB, _bB, 0, dh_a);
    }

    // ---- epilogue: combine halves in fp32, relu, contract with w2 slice ----
#pragma unroll
    for (int i = 0; i < 4; i++) {
#pragma unroll
        for (int h = 0; h < 2; h++) {
            const int row = mw * 64 + i * 16 + g4 + h * 8;
            float v0[4], v1[4];
#pragma unroll
            for (int j = 0; j < 4; j++) {
                float2 fa = __half22float2(*(const __half2*)&dh_a[i][j][h]);
                float2 fb = __half22float2(*(const __half2*)&dh_b[i][j][h]);
                v0[j] = fmaxf(fa.x + fb.x, 0.0f);
                v1[j] = fmaxf(fa.y + fb.y, 0.0f);
            }
#pragma unroll
            for (int c = 0; c < CDIM; c++) {
                float s = 0.0f;
#pragma unroll
                for (int j = 0; j < 4; j++) {
                    float2 w = *(const float2*)&W2s[c * BN + nw * 32 + j * 8 + 2 * t4];
                    s += v0[j] * w.x + v1[j] * w.y;
                }
                s += __shfl_xor_sync(0xFFFFFFFFu, s, 1);
                s += __shfl_xor_sync(0xFFFFFFFFu, s, 2);
                if (t4 == 0) atomicAdd(&Part[row * CDIM + c], s);
            }
        }
    }
    __syncthreads();

    float* outp = g_part + (size_t)nt * (MDIM * CDIM) + (size_t)(mt * BM) * CDIM;
    for (int p = tid; p < BM * CDIM; p += GTHREADS) outp[p] = Part[p];
#undef STAGE_FULL
#undef COMPUTE_STAGE
#undef COMPUTE_KS
#undef ISSUE_STAGE
}

// ---------------- reduce partials + log_softmax ----------------
__global__ void k_reduce(float* __restrict__ out) {   // <<<512, 320>>>
    const int tid = threadIdx.x;
    const int base = blockIdx.x * 32 * CDIM;
    float s = 0.0f;
#pragma unroll 8
    for (int nt = 0; nt < NT2; nt++)
        s += g_part[(size_t)nt * (MDIM * CDIM) + base + tid];
    __shared__ float L[32 * CDIM];
    L[tid] = s;
    __syncthreads();
    const int rl = tid / CDIM;
    float m = -INFINITY;
#pragma unroll
    for (int c = 0; c < CDIM; c++) m = fmaxf(m, L[rl * CDIM + c]);
    float se = 0.0f;
#pragma unroll
    for (int c = 0; c < CDIM; c++) se += expf(L[rl * CDIM + c] - m);
    out[base + tid] = s - m - logf(se);
}

// ---------------- launch ----------------
extern "C" void kernel_launch(void* const* d_in, const int* in_sizes, int n_in,
                              void* d_out, int out_size) {
    const float* x  = (const float*)d_in[0];
    const float* w1 = (const float*)d_in[1];
    const float* s1 = (const float*)d_in[2];
    const float* w2 = (const float*)d_in[3];
    const float* s2 = (const float*)d_in[4];
    float* out = (float*)d_out;

    cudaFuncSetAttribute(k_gemm1, cudaFuncAttributeMaxDynamicSharedMemorySize, SMEM_TOTAL);

    // launch order is load-bearing: ncu captures launch index 3 -> k_gemm1.
    k_select<<<SEL_NB, 256>>>(s1, NK1, J1, 0);                       // 0
    k_select2_w2m<<<1, 1024>>>(s2, w2, NK2, J2);                     // 1
    k_prep<<<W1_BLOCKS + XH_BLOCKS, 256>>>(w1, s1, x);               // 2
    dim3 grid(NT2, MDIM / BM);   // (64, 128)
    k_gemm1<<<grid, GTHREADS, SMEM_TOTAL>>>();                       // 3  <- ncu target
    k_reduce<<<MDIM / 32, 32 * CDIM>>>(out);                         // 4
}